// round 3
// baseline (speedup 1.0000x reference)
#include <cuda_runtime.h>
#include <math.h>

// ---------------- problem constants ----------------
#define BATCH   32
#define HW      56
#define DIM     256
#define WS      7
#define SHIFT   3
#define NH      8
#define HD      32
#define NTOK    49
#define NWIN    64
#define BW      (BATCH*NWIN)
#define MTOK    (BATCH*HW*HW)   // 100352
#define SCALE   0.17677669529663687f

// ---------------- scratch ----------------
__device__ float g_xw  [(size_t)MTOK * 256];
__device__ float g_qkv [(size_t)MTOK * 768];
__device__ float g_xres[(size_t)MTOK * 256];
__device__ float g_h1  [(size_t)MTOK * 1024];
__device__ float g_bias[NH * NTOK * NTOK];

// ---------------- rel-pos bias ----------------
__global__ void bias_kernel(const float* __restrict__ rel_table, float* __restrict__ bias)
{
    int i = blockIdx.x * 256 + threadIdx.x;
    if (i >= NH * NTOK * NTOK) return;
    int h = i / (NTOK*NTOK), rem = i % (NTOK*NTOK);
    int n = rem / NTOK, m = rem % NTOK;
    int rn = n / 7, cn = n % 7, rm = m / 7, cm = m % 7;
    int idx = (rn - rm + 6) * 13 + (cn - cm + 6);
    bias[i] = rel_table[idx * NH + h];
}

// ---------------- LayerNorm ----------------
template<int PERM>
__global__ void __launch_bounds__(256) ln_kernel(
    const float* __restrict__ in, float* __restrict__ out,
    const float* __restrict__ gam, const float* __restrict__ bet)
{
    int row = blockIdx.x;
    int src;
    if (PERM) {
        int bw = row / NTOK, t = row % NTOK;
        int b = bw >> 6, w = bw & 63;
        int wh = w >> 3, ww = w & 7;
        int r = t / 7, c = t % 7;
        int gh = wh * 7 + r + SHIFT; if (gh >= HW) gh -= HW;
        int gw = ww * 7 + c + SHIFT; if (gw >= HW) gw -= HW;
        src = (b * (HW*HW) + gh * HW + gw) * DIM;
    } else {
        src = row * DIM;
    }
    int dst = row * DIM;
    int tid = threadIdx.x;
    float val = in[src + tid];

    float s = val, q = val * val;
    #pragma unroll
    for (int o = 16; o > 0; o >>= 1) {
        s += __shfl_down_sync(0xFFFFFFFFu, s, o);
        q += __shfl_down_sync(0xFFFFFFFFu, q, o);
    }
    __shared__ float rs[8], rq[8];
    __shared__ float smu, srstd;
    int wid = tid >> 5, lane = tid & 31;
    if (lane == 0) { rs[wid] = s; rq[wid] = q; }
    __syncthreads();
    if (tid == 0) {
        float S = 0.f, Q = 0.f;
        #pragma unroll
        for (int i = 0; i < 8; i++) { S += rs[i]; Q += rq[i]; }
        float mu = S * (1.0f/DIM);
        smu = mu;
        srstd = rsqrtf(Q * (1.0f/DIM) - mu*mu + 1e-5f);
    }
    __syncthreads();
    out[dst + tid] = (val - smu) * srstd * gam[tid] + bet[tid];
}

// ---------------- tf32 warp-MMA GEMM ----------------
// C[M,N] = A[M,K] @ B[N,K]^T + bias. Block 128x128, BK=16, double-buffered.
// 8 warps = 2(M) x 4(N); warp tile 64x32.

__device__ __forceinline__ unsigned f2tf(float f) {
    unsigned u; asm("cvt.rna.tf32.f32 %0, %1;" : "=r"(u) : "f"(f)); return u;
}

__device__ __forceinline__ void mma_tf32(float* c, const unsigned* a, const unsigned* b) {
    asm("mma.sync.aligned.m16n8k8.row.col.f32.tf32.tf32.f32 "
        "{%0,%1,%2,%3},{%4,%5,%6,%7},{%8,%9},{%0,%1,%2,%3};"
        : "+f"(c[0]), "+f"(c[1]), "+f"(c[2]), "+f"(c[3])
        : "r"(a[0]), "r"(a[1]), "r"(a[2]), "r"(a[3]), "r"(b[0]), "r"(b[1]));
}

#define GBM 128
#define GBN 128
#define GBK 16

template<int EPI>
__global__ void __launch_bounds__(256) mma_gemm(
    const float* __restrict__ A, const float* __restrict__ B,
    const float* __restrict__ bias, float* __restrict__ C,
    const float* __restrict__ res, int M, int Nn, int K)
{
    __shared__ float As[2][GBM][GBK + 4];
    __shared__ float Bs[2][GBN][GBK + 4];

    const int tid = threadIdx.x;
    const int lane = tid & 31, wid = tid >> 5;
    const int wm = wid >> 2, wn = wid & 3;      // 2 x 4 warps
    const int gid = lane >> 2, tig = lane & 3;
    const int m0 = blockIdx.y * GBM, n0 = blockIdx.x * GBN;

    const int lrow = tid >> 2;          // 0..63
    const int lcol = (tid & 3) * 4;     // 0,4,8,12

    float c[4][4][4];
    #pragma unroll
    for (int i = 0; i < 4; i++)
        #pragma unroll
        for (int j = 0; j < 4; j++)
            #pragma unroll
            for (int r = 0; r < 4; r++) c[i][j][r] = 0.f;

    float4 ar[2], br[2];

    // prefetch K-chunk 0
    #pragma unroll
    for (int p = 0; p < 2; p++) {
        ar[p] = *(const float4*)&A[(size_t)(m0 + lrow + p*64) * K + lcol];
        br[p] = *(const float4*)&B[(size_t)(n0 + lrow + p*64) * K + lcol];
    }
    // store chunk 0
    #pragma unroll
    for (int p = 0; p < 2; p++) {
        int r = lrow + p * 64;
        As[0][r][lcol+0] = __uint_as_float(f2tf(ar[p].x));
        As[0][r][lcol+1] = __uint_as_float(f2tf(ar[p].y));
        As[0][r][lcol+2] = __uint_as_float(f2tf(ar[p].z));
        As[0][r][lcol+3] = __uint_as_float(f2tf(ar[p].w));
        Bs[0][r][lcol+0] = __uint_as_float(f2tf(br[p].x));
        Bs[0][r][lcol+1] = __uint_as_float(f2tf(br[p].y));
        Bs[0][r][lcol+2] = __uint_as_float(f2tf(br[p].z));
        Bs[0][r][lcol+3] = __uint_as_float(f2tf(br[p].w));
    }
    __syncthreads();

    const int nk = K / GBK;
    for (int kt = 0; kt < nk; kt++) {
        const int cur = kt & 1;
        if (kt + 1 < nk) {
            int kb = (kt + 1) * GBK;
            #pragma unroll
            for (int p = 0; p < 2; p++) {
                ar[p] = *(const float4*)&A[(size_t)(m0 + lrow + p*64) * K + kb + lcol];
                br[p] = *(const float4*)&B[(size_t)(n0 + lrow + p*64) * K + kb + lcol];
            }
        }

        #pragma unroll
        for (int kk = 0; kk < 2; kk++) {
            const int kb = kk * 8;
            unsigned af[4][4], bf[4][2];
            #pragma unroll
            for (int mt = 0; mt < 4; mt++) {
                int rb = wm * 64 + mt * 16;
                af[mt][0] = __float_as_uint(As[cur][rb + gid    ][kb + tig    ]);
                af[mt][1] = __float_as_uint(As[cur][rb + gid + 8][kb + tig    ]);
                af[mt][2] = __float_as_uint(As[cur][rb + gid    ][kb + tig + 4]);
                af[mt][3] = __float_as_uint(As[cur][rb + gid + 8][kb + tig + 4]);
            }
            #pragma unroll
            for (int nt = 0; nt < 4; nt++) {
                int nb = wn * 32 + nt * 8;
                bf[nt][0] = __float_as_uint(Bs[cur][nb + gid][kb + tig    ]);
                bf[nt][1] = __float_as_uint(Bs[cur][nb + gid][kb + tig + 4]);
            }
            #pragma unroll
            for (int mt = 0; mt < 4; mt++)
                #pragma unroll
                for (int nt = 0; nt < 4; nt++)
                    mma_tf32(c[mt][nt], af[mt], bf[nt]);
        }

        if (kt + 1 < nk) {
            const int nxt = (kt + 1) & 1;
            #pragma unroll
            for (int p = 0; p < 2; p++) {
                int r = lrow + p * 64;
                As[nxt][r][lcol+0] = __uint_as_float(f2tf(ar[p].x));
                As[nxt][r][lcol+1] = __uint_as_float(f2tf(ar[p].y));
                As[nxt][r][lcol+2] = __uint_as_float(f2tf(ar[p].z));
                As[nxt][r][lcol+3] = __uint_as_float(f2tf(ar[p].w));
                Bs[nxt][r][lcol+0] = __uint_as_float(f2tf(br[p].x));
                Bs[nxt][r][lcol+1] = __uint_as_float(f2tf(br[p].y));
                Bs[nxt][r][lcol+2] = __uint_as_float(f2tf(br[p].z));
                Bs[nxt][r][lcol+3] = __uint_as_float(f2tf(br[p].w));
            }
            __syncthreads();
        }
    }

    // ---------------- epilogue ----------------
    #pragma unroll
    for (int mt = 0; mt < 4; mt++) {
        #pragma unroll
        for (int nt = 0; nt < 4; nt++) {
            int r0 = m0 + wm * 64 + mt * 16 + gid;
            int r1 = r0 + 8;
            int cb = n0 + wn * 32 + nt * 8 + 2 * tig;
            float bs0 = bias[cb], bs1 = bias[cb + 1];
            float v00 = c[mt][nt][0] + bs0, v01 = c[mt][nt][1] + bs1;
            float v10 = c[mt][nt][2] + bs0, v11 = c[mt][nt][3] + bs1;

            if (EPI == 0) {
                if (cb < 256) { v00 *= SCALE; v01 *= SCALE; v10 *= SCALE; v11 *= SCALE; }
                *(float2*)&C[(size_t)r0 * Nn + cb] = make_float2(v00, v01);
                *(float2*)&C[(size_t)r1 * Nn + cb] = make_float2(v10, v11);
            } else if (EPI == 1) {
                const float kk = 0.70710678118654752f;
                v00 = 0.5f * v00 * (1.f + erff(v00 * kk));
                v01 = 0.5f * v01 * (1.f + erff(v01 * kk));
                v10 = 0.5f * v10 * (1.f + erff(v10 * kk));
                v11 = 0.5f * v11 * (1.f + erff(v11 * kk));
                *(float2*)&C[(size_t)r0 * Nn + cb] = make_float2(v00, v01);
                *(float2*)&C[(size_t)r1 * Nn + cb] = make_float2(v10, v11);
            } else if (EPI == 2) {
                #pragma unroll
                for (int rr = 0; rr < 2; rr++) {
                    int m = rr ? r1 : r0;
                    float va = rr ? v10 : v00, vb = rr ? v11 : v01;
                    int bw = m / NTOK, t = m % NTOK;
                    int b = bw >> 6, w = bw & 63;
                    int wh = w >> 3, ww = w & 7;
                    int r = t / 7, cc = t % 7;
                    int gh = wh * 7 + r + SHIFT; if (gh >= HW) gh -= HW;
                    int gw = ww * 7 + cc + SHIFT; if (gw >= HW) gw -= HW;
                    size_t dst = (size_t)(b * (HW*HW) + gh * HW + gw) * DIM + cb;
                    float2 rv = *(const float2*)&res[dst];
                    *(float2*)&C[dst] = make_float2(va + rv.x, vb + rv.y);
                }
            } else { // EPI == 3
                size_t d0 = (size_t)r0 * Nn + cb, d1 = (size_t)r1 * Nn + cb;
                float2 ra = *(const float2*)&res[d0];
                float2 rb2 = *(const float2*)&res[d1];
                *(float2*)&C[d0] = make_float2(v00 + ra.x, v01 + ra.y);
                *(float2*)&C[d1] = make_float2(v10 + rb2.x, v11 + rb2.y);
            }
        }
    }
}

// ---------------- attention ----------------
__global__ void __launch_bounds__(256, 4) attn_kernel(
    const float* __restrict__ qkv, const float* __restrict__ bias,
    float* __restrict__ out)
{
    __shared__ float sq [NTOK][36];
    __shared__ float skT[HD][NTOK + 1];
    __shared__ float sv [NTOK][36];
    __shared__ float sp [NTOK][50];
    __shared__ int   regn[NTOK];

    int bw = blockIdx.x >> 3;
    int h  = blockIdx.x & 7;
    int tid = threadIdx.x, lane = tid & 31, wid = tid >> 5;

    if (tid < NTOK) {
        int w = bw & 63;
        int wh = w >> 3, ww = w & 7;
        int r = tid / 7, c = tid % 7;
        int gh = wh * 7 + r, gw = ww * 7 + c;
        int rh = (gh < HW - WS) ? 0 : ((gh < HW - SHIFT) ? 1 : 2);
        int rw = (gw < HW - WS) ? 0 : ((gw < HW - SHIFT) ? 1 : 2);
        regn[tid] = rh * 3 + rw;
    }
    // vectorized load of q,k,v (float4 over head dim)
    for (int i = tid; i < NTOK * 8; i += 256) {
        int n = i >> 3, d4 = (i & 7) * 4;
        size_t base = (size_t)(bw * NTOK + n) * 768 + h * HD + d4;
        float4 q = *(const float4*)&qkv[base];
        float4 k = *(const float4*)&qkv[base + 256];
        float4 v = *(const float4*)&qkv[base + 512];
        *(float4*)&sq[n][d4] = q;
        skT[d4+0][n] = k.x; skT[d4+1][n] = k.y;
        skT[d4+2][n] = k.z; skT[d4+3][n] = k.w;
        *(float4*)&sv[n][d4] = v;
    }
    __syncthreads();

    const float* brow = bias + h * (NTOK * NTOK);
    bool has1 = lane < (NTOK - 32);
    int m1 = has1 ? lane + 32 : lane;

    for (int n = wid; n < NTOK; n += 8) {
        float a0 = 0.f, a1 = 0.f;
        #pragma unroll
        for (int d = 0; d < HD; d++) {
            float qd = sq[n][d];
            a0 = fmaf(qd, skT[d][lane], a0);
            a1 = fmaf(qd, skT[d][m1],   a1);
        }
        int rn = regn[n];
        a0 += brow[n * NTOK + lane] + ((rn != regn[lane]) ? -100.f : 0.f);
        if (has1) a1 += brow[n * NTOK + m1] + ((rn != regn[m1]) ? -100.f : 0.f);
        else      a1 = -1e30f;

        float mx = fmaxf(a0, a1);
        #pragma unroll
        for (int o = 16; o > 0; o >>= 1) mx = fmaxf(mx, __shfl_xor_sync(0xFFFFFFFFu, mx, o));
        float e0 = __expf(a0 - mx);
        float e1 = has1 ? __expf(a1 - mx) : 0.f;
        float sm = e0 + e1;
        #pragma unroll
        for (int o = 16; o > 0; o >>= 1) sm += __shfl_xor_sync(0xFFFFFFFFu, sm, o);
        float inv = 1.f / sm;
        sp[n][lane] = e0 * inv;
        if (has1) sp[n][lane + 32] = e1 * inv;
    }
    __syncthreads();

    // PV: float4 over head dim; per m: 1 broadcast + 1 LDS.128 for 8 FMA
    for (int s = tid; s < NTOK * 8; s += 256) {
        int n = s >> 3, d4 = (s & 7) * 4;
        float ax = 0.f, ay = 0.f, az = 0.f, aw = 0.f;
        #pragma unroll
        for (int m = 0; m < NTOK; m++) {
            float p = sp[n][m];
            float4 v = *(const float4*)&sv[m][d4];
            ax = fmaf(p, v.x, ax); ay = fmaf(p, v.y, ay);
            az = fmaf(p, v.z, az); aw = fmaf(p, v.w, aw);
        }
        *(float4*)&out[(size_t)(bw * NTOK + n) * 256 + h * HD + d4] =
            make_float4(ax, ay, az, aw);
    }
}

// ---------------- launcher ----------------
extern "C" void kernel_launch(void* const* d_in, const int* in_sizes, int n_in,
                              void* d_out, int out_size)
{
    (void)in_sizes; (void)n_in; (void)out_size;
    const float* x        = (const float*)d_in[0];
    const float* norm1_g  = (const float*)d_in[1];
    const float* norm1_b  = (const float*)d_in[2];
    const float* qkv_w    = (const float*)d_in[3];
    const float* qkv_b    = (const float*)d_in[4];
    const float* rel_tab  = (const float*)d_in[5];
    const float* proj_w   = (const float*)d_in[6];
    const float* proj_b   = (const float*)d_in[7];
    const float* norm2_g  = (const float*)d_in[8];
    const float* norm2_b  = (const float*)d_in[9];
    const float* fc1_w    = (const float*)d_in[10];
    const float* fc1_b    = (const float*)d_in[11];
    const float* fc2_w    = (const float*)d_in[12];
    const float* fc2_b    = (const float*)d_in[13];
    float* out = (float*)d_out;

    float *p_xw, *p_qkv, *p_xres, *p_h1, *p_bias;
    cudaGetSymbolAddress((void**)&p_xw,   g_xw);
    cudaGetSymbolAddress((void**)&p_qkv,  g_qkv);
    cudaGetSymbolAddress((void**)&p_xres, g_xres);
    cudaGetSymbolAddress((void**)&p_h1,   g_h1);
    cudaGetSymbolAddress((void**)&p_bias, g_bias);

    const int M = MTOK;

    bias_kernel<<<(NH*NTOK*NTOK + 255)/256, 256>>>(rel_tab, p_bias);
    ln_kernel<1><<<M, 256>>>(x, p_xw, norm1_g, norm1_b);
    mma_gemm<0><<<dim3(768/GBN, M/GBM), 256>>>(p_xw, qkv_w, qkv_b, p_qkv, nullptr, M, 768, 256);
    attn_kernel<<<BW * NH, 256>>>(p_qkv, p_bias, p_xw);
    mma_gemm<2><<<dim3(256/GBN, M/GBM), 256>>>(p_xw, proj_w, proj_b, p_xres, x, M, 256, 256);
    ln_kernel<0><<<M, 256>>>(p_xres, p_xw, norm2_g, norm2_b);
    mma_gemm<1><<<dim3(1024/GBN, M/GBM), 256>>>(p_xw, fc1_w, fc1_b, p_h1, nullptr, M, 1024, 256);
    mma_gemm<3><<<dim3(256/GBN, M/GBM), 256>>>(p_h1, fc2_w, fc2_b, out, p_xres, M, 256, 1024);
}

// round 5
// speedup vs baseline: 1.6295x; 1.6295x over previous
#include <cuda_runtime.h>
#include <cuda_fp16.h>
#include <math.h>
#include <stdint.h>

// ---------------- problem constants ----------------
#define BATCH   32
#define HW      56
#define DIM     256
#define WS      7
#define SHIFT   3
#define NH      8
#define HD      32
#define NTOK    49
#define NWIN    64
#define BW      (BATCH*NWIN)
#define MTOK    (BATCH*HW*HW)   // 100352
#define SCALE   0.17677669529663687f

// ---------------- scratch ----------------
__device__ __half hb_a  [(size_t)MTOK * 256];   // LN1 out -> attn out -> LN2 out
__device__ __half hb_qkv[(size_t)MTOK * 768];
__device__ __half hb_h1 [(size_t)MTOK * 1024];
__device__ float  g_xres[(size_t)MTOK * 256];
__device__ float  g_bias[NH * NTOK * NTOK];
__device__ __half hw_qkv [768 * 256];
__device__ __half hw_proj[256 * 256];
__device__ __half hw_fc1 [1024 * 256];
__device__ __half hw_fc2 [256 * 1024];

// ---------------- weight fp32 -> fp16 ----------------
__global__ void wconv_kernel(const float* __restrict__ w, __half* __restrict__ o, int n)
{
    int i = blockIdx.x * 256 + threadIdx.x;
    if (i < n) o[i] = __float2half(w[i]);
}

// ---------------- rel-pos bias ----------------
__global__ void bias_kernel(const float* __restrict__ rel_table, float* __restrict__ bias)
{
    int i = blockIdx.x * 256 + threadIdx.x;
    if (i >= NH * NTOK * NTOK) return;
    int h = i / (NTOK*NTOK), rem = i % (NTOK*NTOK);
    int n = rem / NTOK, m = rem % NTOK;
    int rn = n / 7, cn = n % 7, rm = m / 7, cm = m % 7;
    int idx = (rn - rm + 6) * 13 + (cn - cm + 6);
    bias[i] = rel_table[idx * NH + h];
}

// ---------------- LayerNorm (fp32 in, fp16 out) ----------------
template<int PERM>
__global__ void __launch_bounds__(256) ln_kernel(
    const float* __restrict__ in, __half* __restrict__ out,
    const float* __restrict__ gam, const float* __restrict__ bet)
{
    int row = blockIdx.x;
    int src;
    if (PERM) {
        int bw = row / NTOK, t = row % NTOK;
        int b = bw >> 6, w = bw & 63;
        int wh = w >> 3, ww = w & 7;
        int r = t / 7, c = t % 7;
        int gh = wh * 7 + r + SHIFT; if (gh >= HW) gh -= HW;
        int gw = ww * 7 + c + SHIFT; if (gw >= HW) gw -= HW;
        src = (b * (HW*HW) + gh * HW + gw) * DIM;
    } else {
        src = row * DIM;
    }
    int dst = row * DIM;
    int tid = threadIdx.x;
    float val = in[src + tid];

    float s = val, q = val * val;
    #pragma unroll
    for (int o = 16; o > 0; o >>= 1) {
        s += __shfl_down_sync(0xFFFFFFFFu, s, o);
        q += __shfl_down_sync(0xFFFFFFFFu, q, o);
    }
    __shared__ float rs[8], rq[8];
    __shared__ float smu, srstd;
    int wid = tid >> 5, lane = tid & 31;
    if (lane == 0) { rs[wid] = s; rq[wid] = q; }
    __syncthreads();
    if (tid == 0) {
        float S = 0.f, Q = 0.f;
        #pragma unroll
        for (int i = 0; i < 8; i++) { S += rs[i]; Q += rq[i]; }
        float mu = S * (1.0f/DIM);
        smu = mu;
        srstd = rsqrtf(Q * (1.0f/DIM) - mu*mu + 1e-5f);
    }
    __syncthreads();
    out[dst + tid] = __float2half((val - smu) * srstd * gam[tid] + bet[tid]);
}

// ---------------- fp16 warp-MMA GEMM ----------------
// C[M,N] = A[M,K] @ B[N,K]^T + bias. A,B half in gmem. fp32 accum.
// Block 128x128, BK=32 halves, double-buffered. 8 warps 2(M)x4(N), warp 64x32.
// EPI 0: qkv  (scale q cols, half out)
// EPI 1: fc1  (gelu, half out)
// EPI 2: proj (window-reverse + roll + residual, float out)
// EPI 3: fc2  (residual, float out)

__device__ __forceinline__ void mma_f16(float* c, const unsigned* a, const unsigned* b) {
    asm("mma.sync.aligned.m16n8k16.row.col.f32.f16.f16.f32 "
        "{%0,%1,%2,%3},{%4,%5,%6,%7},{%8,%9},{%0,%1,%2,%3};"
        : "+f"(c[0]), "+f"(c[1]), "+f"(c[2]), "+f"(c[3])
        : "r"(a[0]), "r"(a[1]), "r"(a[2]), "r"(a[3]), "r"(b[0]), "r"(b[1]));
}

#define SST 20   // smem row stride in uint32 (conflict-free for frag loads)

template<int EPI>
__global__ void __launch_bounds__(256) hgemm(
    const __half* __restrict__ A, const __half* __restrict__ B,
    const float* __restrict__ bias, float* __restrict__ Cf, __half* __restrict__ Ch,
    const float* __restrict__ res, int M, int Nn, int K)
{
    __shared__ uint32_t As[2][128][SST];
    __shared__ uint32_t Bs[2][128][SST];

    const int tid = threadIdx.x;
    const int lane = tid & 31, wid = tid >> 5;
    const int wm = wid >> 2, wn = wid & 3;
    const int gid = lane >> 2, tig = lane & 3;
    const int m0 = blockIdx.y * 128, n0 = blockIdx.x * 128;

    float c[4][4][4];
    #pragma unroll
    for (int i = 0; i < 4; i++)
        #pragma unroll
        for (int j = 0; j < 4; j++)
            #pragma unroll
            for (int r = 0; r < 4; r++) c[i][j][r] = 0.f;

    // loader: 512 uint4 slots per operand (128 rows x 4 cols of 8 halves)
    // thread handles slots tid and tid+256
    const int r0l = tid >> 2,   q0l = tid & 3;          // slot tid
    const int r1l = r0l + 64,   q1l = q0l;              // slot tid+256

    uint4 a0v, a1v, b0v, b1v;
    // prologue: stage 0
    a0v = *(const uint4*)&A[(size_t)(m0 + r0l) * K + q0l * 8];
    a1v = *(const uint4*)&A[(size_t)(m0 + r1l) * K + q1l * 8];
    b0v = *(const uint4*)&B[(size_t)(n0 + r0l) * K + q0l * 8];
    b1v = *(const uint4*)&B[(size_t)(n0 + r1l) * K + q1l * 8];
    *(uint4*)&As[0][r0l][q0l * 4] = a0v;
    *(uint4*)&As[0][r1l][q1l * 4] = a1v;
    *(uint4*)&Bs[0][r0l][q0l * 4] = b0v;
    *(uint4*)&Bs[0][r1l][q1l * 4] = b1v;
    __syncthreads();

    const int nk = K >> 5;
    for (int kt = 0; kt < nk; kt++) {
        const int cur = kt & 1;
        if (kt + 1 < nk) {
            const size_t kb = (size_t)(kt + 1) * 32;
            a0v = *(const uint4*)&A[(size_t)(m0 + r0l) * K + kb + q0l * 8];
            a1v = *(const uint4*)&A[(size_t)(m0 + r1l) * K + kb + q1l * 8];
            b0v = *(const uint4*)&B[(size_t)(n0 + r0l) * K + kb + q0l * 8];
            b1v = *(const uint4*)&B[(size_t)(n0 + r1l) * K + kb + q1l * 8];
        }

        #pragma unroll
        for (int kk = 0; kk < 2; kk++) {
            const int base = kk * 8;
            unsigned af[4][4], bf[4][2];
            #pragma unroll
            for (int mt = 0; mt < 4; mt++) {
                int rb = wm * 64 + mt * 16;
                af[mt][0] = As[cur][rb + gid    ][base + tig    ];
                af[mt][1] = As[cur][rb + gid + 8][base + tig    ];
                af[mt][2] = As[cur][rb + gid    ][base + tig + 4];
                af[mt][3] = As[cur][rb + gid + 8][base + tig + 4];
            }
            #pragma unroll
            for (int nt = 0; nt < 4; nt++) {
                int nb = wn * 32 + nt * 8;
                bf[nt][0] = Bs[cur][nb + gid][base + tig    ];
                bf[nt][1] = Bs[cur][nb + gid][base + tig + 4];
            }
            #pragma unroll
            for (int mt = 0; mt < 4; mt++)
                #pragma unroll
                for (int nt = 0; nt < 4; nt++)
                    mma_f16(c[mt][nt], af[mt], bf[nt]);
        }

        if (kt + 1 < nk) {
            const int nxt = (kt + 1) & 1;
            *(uint4*)&As[nxt][r0l][q0l * 4] = a0v;
            *(uint4*)&As[nxt][r1l][q1l * 4] = a1v;
            *(uint4*)&Bs[nxt][r0l][q0l * 4] = b0v;
            *(uint4*)&Bs[nxt][r1l][q1l * 4] = b1v;
            __syncthreads();
        }
    }

    // ---------------- epilogue ----------------
    #pragma unroll
    for (int mt = 0; mt < 4; mt++) {
        #pragma unroll
        for (int nt = 0; nt < 4; nt++) {
            int r0 = m0 + wm * 64 + mt * 16 + gid;
            int r1 = r0 + 8;
            int cb = n0 + wn * 32 + nt * 8 + 2 * tig;
            float bs0 = bias[cb], bs1 = bias[cb + 1];
            float v00 = c[mt][nt][0] + bs0, v01 = c[mt][nt][1] + bs1;
            float v10 = c[mt][nt][2] + bs0, v11 = c[mt][nt][3] + bs1;

            if (EPI == 0) {
                if (cb < 256) { v00 *= SCALE; v01 *= SCALE; v10 *= SCALE; v11 *= SCALE; }
                *(__half2*)&Ch[(size_t)r0 * Nn + cb] = __floats2half2_rn(v00, v01);
                *(__half2*)&Ch[(size_t)r1 * Nn + cb] = __floats2half2_rn(v10, v11);
            } else if (EPI == 1) {
                const float kk = 0.70710678118654752f;
                v00 = 0.5f * v00 * (1.f + erff(v00 * kk));
                v01 = 0.5f * v01 * (1.f + erff(v01 * kk));
                v10 = 0.5f * v10 * (1.f + erff(v10 * kk));
                v11 = 0.5f * v11 * (1.f + erff(v11 * kk));
                *(__half2*)&Ch[(size_t)r0 * Nn + cb] = __floats2half2_rn(v00, v01);
                *(__half2*)&Ch[(size_t)r1 * Nn + cb] = __floats2half2_rn(v10, v11);
            } else if (EPI == 2) {
                #pragma unroll
                for (int rr = 0; rr < 2; rr++) {
                    int m = rr ? r1 : r0;
                    float va = rr ? v10 : v00, vb = rr ? v11 : v01;
                    int bw = m / NTOK, t = m % NTOK;
                    int b = bw >> 6, w = bw & 63;
                    int wh = w >> 3, ww = w & 7;
                    int r = t / 7, cc = t % 7;
                    int gh = wh * 7 + r + SHIFT; if (gh >= HW) gh -= HW;
                    int gw = ww * 7 + cc + SHIFT; if (gw >= HW) gw -= HW;
                    size_t dst = (size_t)(b * (HW*HW) + gh * HW + gw) * DIM + cb;
                    float2 rv = *(const float2*)&res[dst];
                    *(float2*)&Cf[dst] = make_float2(va + rv.x, vb + rv.y);
                }
            } else { // EPI == 3
                size_t d0 = (size_t)r0 * Nn + cb, d1 = (size_t)r1 * Nn + cb;
                float2 ra = *(const float2*)&res[d0];
                float2 rb2 = *(const float2*)&res[d1];
                *(float2*)&Cf[d0] = make_float2(v00 + ra.x, v01 + ra.y);
                *(float2*)&Cf[d1] = make_float2(v10 + rb2.x, v11 + rb2.y);
            }
        }
    }
}

// ---------------- attention: half qkv in, half out ----------------
__global__ void __launch_bounds__(256) attn_kernel(
    const __half* __restrict__ qkv, const float* __restrict__ bias,
    __half* __restrict__ out)
{
    __shared__ float sq [NTOK][36];
    __shared__ float skT[HD][NTOK + 1];
    __shared__ float sv [NTOK][36];
    __shared__ float sp [NTOK][50];
    __shared__ int   regn[NTOK];

    int bw = blockIdx.x >> 3;
    int h  = blockIdx.x & 7;
    int tid = threadIdx.x, lane = tid & 31, wid = tid >> 5;

    if (tid < NTOK) {
        int w = bw & 63;
        int wh = w >> 3, ww = w & 7;
        int r = tid / 7, c = tid % 7;
        int gh = wh * 7 + r, gw = ww * 7 + c;
        int rh = (gh < HW - WS) ? 0 : ((gh < HW - SHIFT) ? 1 : 2);
        int rw = (gw < HW - WS) ? 0 : ((gw < HW - SHIFT) ? 1 : 2);
        regn[tid] = rh * 3 + rw;
    }
    // load q,k,v: 8 halves per slot
    for (int i = tid; i < NTOK * 4; i += 256) {
        int n = i >> 2, d8 = (i & 3) * 8;
        size_t basep = (size_t)(bw * NTOK + n) * 768 + h * HD + d8;
        uint4 qu = *(const uint4*)&qkv[basep];
        uint4 ku = *(const uint4*)&qkv[basep + 256];
        uint4 vu = *(const uint4*)&qkv[basep + 512];
        const __half2* qh = (const __half2*)&qu;
        const __half2* kh = (const __half2*)&ku;
        const __half2* vh = (const __half2*)&vu;
        #pragma unroll
        for (int j = 0; j < 4; j++) {
            float2 qf = __half22float2(qh[j]);
            float2 kf = __half22float2(kh[j]);
            float2 vf = __half22float2(vh[j]);
            sq[n][d8 + 2*j]     = qf.x; sq[n][d8 + 2*j + 1] = qf.y;
            skT[d8 + 2*j][n]    = kf.x; skT[d8 + 2*j + 1][n] = kf.y;
            sv[n][d8 + 2*j]     = vf.x; sv[n][d8 + 2*j + 1] = vf.y;
        }
    }
    __syncthreads();

    const float* brow = bias + h * (NTOK * NTOK);
    bool has1 = lane < (NTOK - 32);
    int m1 = has1 ? lane + 32 : lane;

    for (int n = wid; n < NTOK; n += 8) {
        float a0 = 0.f, a1 = 0.f;
        #pragma unroll
        for (int d = 0; d < HD; d++) {
            float qd = sq[n][d];
            a0 = fmaf(qd, skT[d][lane], a0);
            a1 = fmaf(qd, skT[d][m1],   a1);
        }
        int rn = regn[n];
        a0 += brow[n * NTOK + lane] + ((rn != regn[lane]) ? -100.f : 0.f);
        if (has1) a1 += brow[n * NTOK + m1] + ((rn != regn[m1]) ? -100.f : 0.f);
        else      a1 = -1e30f;

        float mx = fmaxf(a0, a1);
        #pragma unroll
        for (int o = 16; o > 0; o >>= 1) mx = fmaxf(mx, __shfl_xor_sync(0xFFFFFFFFu, mx, o));
        float e0 = __expf(a0 - mx);
        float e1 = has1 ? __expf(a1 - mx) : 0.f;
        float sm = e0 + e1;
        #pragma unroll
        for (int o = 16; o > 0; o >>= 1) sm += __shfl_xor_sync(0xFFFFFFFFu, sm, o);
        float inv = 1.f / sm;
        sp[n][lane] = e0 * inv;
        if (has1) sp[n][lane + 32] = e1 * inv;
    }
    __syncthreads();

    // PV: float4 over head dim
    for (int s = tid; s < NTOK * 8; s += 256) {
        int n = s >> 3, d4 = (s & 7) * 4;
        float ax = 0.f, ay = 0.f, az = 0.f, aw = 0.f;
        #pragma unroll
        for (int m = 0; m < NTOK; m++) {
            float p = sp[n][m];
            float4 v = *(const float4*)&sv[m][d4];
            ax = fmaf(p, v.x, ax); ay = fmaf(p, v.y, ay);
            az = fmaf(p, v.z, az); aw = fmaf(p, v.w, aw);
        }
        uint2 o2;
        *(__half2*)&o2.x = __floats2half2_rn(ax, ay);
        *(__half2*)&o2.y = __floats2half2_rn(az, aw);
        *(uint2*)&out[(size_t)(bw * NTOK + n) * 256 + h * HD + d4] = o2;
    }
}

// ---------------- launcher ----------------
extern "C" void kernel_launch(void* const* d_in, const int* in_sizes, int n_in,
                              void* d_out, int out_size)
{
    (void)in_sizes; (void)n_in; (void)out_size;
    const float* x        = (const float*)d_in[0];
    const float* norm1_g  = (const float*)d_in[1];
    const float* norm1_b  = (const float*)d_in[2];
    const float* qkv_w    = (const float*)d_in[3];
    const float* qkv_b    = (const float*)d_in[4];
    const float* rel_tab  = (const float*)d_in[5];
    const float* proj_w   = (const float*)d_in[6];
    const float* proj_b   = (const float*)d_in[7];
    const float* norm2_g  = (const float*)d_in[8];
    const float* norm2_b  = (const float*)d_in[9];
    const float* fc1_w    = (const float*)d_in[10];
    const float* fc1_b    = (const float*)d_in[11];
    const float* fc2_w    = (const float*)d_in[12];
    const float* fc2_b    = (const float*)d_in[13];
    float* out = (float*)d_out;

    __half *p_a, *p_qkv, *p_h1, *p_wqkv, *p_wproj, *p_wfc1, *p_wfc2;
    float *p_xres, *p_bias;
    cudaGetSymbolAddress((void**)&p_a,     hb_a);
    cudaGetSymbolAddress((void**)&p_qkv,   hb_qkv);
    cudaGetSymbolAddress((void**)&p_h1,    hb_h1);
    cudaGetSymbolAddress((void**)&p_xres,  g_xres);
    cudaGetSymbolAddress((void**)&p_bias,  g_bias);
    cudaGetSymbolAddress((void**)&p_wqkv,  hw_qkv);
    cudaGetSymbolAddress((void**)&p_wproj, hw_proj);
    cudaGetSymbolAddress((void**)&p_wfc1,  hw_fc1);
    cudaGetSymbolAddress((void**)&p_wfc2,  hw_fc2);

    const int M = MTOK;

    bias_kernel<<<(NH*NTOK*NTOK + 255)/256, 256>>>(rel_tab, p_bias);
    wconv_kernel<<<(768*256 + 255)/256, 256>>>(qkv_w, p_wqkv, 768*256);
    wconv_kernel<<<(256*256 + 255)/256, 256>>>(proj_w, p_wproj, 256*256);
    wconv_kernel<<<(1024*256 + 255)/256, 256>>>(fc1_w, p_wfc1, 1024*256);
    wconv_kernel<<<(256*1024 + 255)/256, 256>>>(fc2_w, p_wfc2, 256*1024);

    ln_kernel<1><<<M, 256>>>(x, p_a, norm1_g, norm1_b);
    hgemm<0><<<dim3(768/128, M/128), 256>>>(p_a, p_wqkv, qkv_b, nullptr, p_qkv, nullptr, M, 768, 256);
    attn_kernel<<<BW * NH, 256>>>(p_qkv, p_bias, p_a);
    hgemm<2><<<dim3(256/128, M/128), 256>>>(p_a, p_wproj, proj_b, p_xres, nullptr, x, M, 256, 256);
    ln_kernel<0><<<M, 256>>>(p_xres, p_a, norm2_g, norm2_b);
    hgemm<1><<<dim3(1024/128, M/128), 256>>>(p_a, p_wfc1, fc1_b, nullptr, p_h1, nullptr, M, 1024, 256);
    hgemm<3><<<dim3(256/128, M/128), 256>>>(p_h1, p_wfc2, fc2_b, out, nullptr, p_xres, M, 256, 1024);
}

// round 6
// speedup vs baseline: 2.1599x; 1.3255x over previous
#include <cuda_runtime.h>
#include <cuda_fp16.h>
#include <math.h>
#include <stdint.h>

// ---------------- problem constants ----------------
#define BATCH   32
#define HW      56
#define DIM     256
#define WS      7
#define SHIFT   3
#define NH      8
#define HD      32
#define NTOK    49
#define NWIN    64
#define BW      (BATCH*NWIN)
#define MTOK    (BATCH*HW*HW)   // 100352
#define SCALE   0.17677669529663687f

// ---------------- scratch ----------------
__device__ __half hb_a  [(size_t)MTOK * 256];
__device__ __half hb_qkv[(size_t)MTOK * 768];
__device__ __half hb_h1 [(size_t)MTOK * 1024];
__device__ float  g_xres[(size_t)MTOK * 256];
__device__ float  g_bias[NH * NTOK * NTOK];
__device__ __half hw_qkv [768 * 256];
__device__ __half hw_proj[256 * 256];
__device__ __half hw_fc1 [1024 * 256];
__device__ __half hw_fc2 [256 * 1024];

// ---------------- weight fp32 -> fp16 ----------------
__global__ void wconv_kernel(const float* __restrict__ w, __half* __restrict__ o, int n)
{
    int i = blockIdx.x * 256 + threadIdx.x;
    if (i < n) o[i] = __float2half(w[i]);
}

// ---------------- rel-pos bias ----------------
__global__ void bias_kernel(const float* __restrict__ rel_table, float* __restrict__ bias)
{
    int i = blockIdx.x * 256 + threadIdx.x;
    if (i >= NH * NTOK * NTOK) return;
    int h = i / (NTOK*NTOK), rem = i % (NTOK*NTOK);
    int n = rem / NTOK, m = rem % NTOK;
    int rn = n / 7, cn = n % 7, rm = m / 7, cm = m % 7;
    int idx = (rn - rm + 6) * 13 + (cn - cm + 6);
    bias[i] = rel_table[idx * NH + h];
}

// ---------------- LayerNorm (fp32 in, fp16 out) ----------------
template<int PERM>
__global__ void __launch_bounds__(256) ln_kernel(
    const float* __restrict__ in, __half* __restrict__ out,
    const float* __restrict__ gam, const float* __restrict__ bet)
{
    int row = blockIdx.x;
    int src;
    if (PERM) {
        int bw = row / NTOK, t = row % NTOK;
        int b = bw >> 6, w = bw & 63;
        int wh = w >> 3, ww = w & 7;
        int r = t / 7, c = t % 7;
        int gh = wh * 7 + r + SHIFT; if (gh >= HW) gh -= HW;
        int gw = ww * 7 + c + SHIFT; if (gw >= HW) gw -= HW;
        src = (b * (HW*HW) + gh * HW + gw) * DIM;
    } else {
        src = row * DIM;
    }
    int dst = row * DIM;
    int tid = threadIdx.x;
    float val = in[src + tid];

    float s = val, q = val * val;
    #pragma unroll
    for (int o = 16; o > 0; o >>= 1) {
        s += __shfl_down_sync(0xFFFFFFFFu, s, o);
        q += __shfl_down_sync(0xFFFFFFFFu, q, o);
    }
    __shared__ float rs[8], rq[8];
    __shared__ float smu, srstd;
    int wid = tid >> 5, lane = tid & 31;
    if (lane == 0) { rs[wid] = s; rq[wid] = q; }
    __syncthreads();
    if (tid == 0) {
        float S = 0.f, Q = 0.f;
        #pragma unroll
        for (int i = 0; i < 8; i++) { S += rs[i]; Q += rq[i]; }
        float mu = S * (1.0f/DIM);
        smu = mu;
        srstd = rsqrtf(Q * (1.0f/DIM) - mu*mu + 1e-5f);
    }
    __syncthreads();
    out[dst + tid] = __float2half((val - smu) * srstd * gam[tid] + bet[tid]);
}

// ---------------- fp16 mma ----------------
__device__ __forceinline__ void mma_f16(float* c, const unsigned* a, const unsigned* b) {
    asm("mma.sync.aligned.m16n8k16.row.col.f32.f16.f16.f32 "
        "{%0,%1,%2,%3},{%4,%5,%6,%7},{%8,%9},{%0,%1,%2,%3};"
        : "+f"(c[0]), "+f"(c[1]), "+f"(c[2]), "+f"(c[3])
        : "r"(a[0]), "r"(a[1]), "r"(a[2]), "r"(a[3]), "r"(b[0]), "r"(b[1]));
}

// ---------------- fp16 warp-MMA GEMM ----------------
#define SST 20

template<int EPI>
__global__ void __launch_bounds__(256) hgemm(
    const __half* __restrict__ A, const __half* __restrict__ B,
    const float* __restrict__ bias, float* __restrict__ Cf, __half* __restrict__ Ch,
    const float* __restrict__ res, int M, int Nn, int K)
{
    __shared__ uint32_t As[2][128][SST];
    __shared__ uint32_t Bs[2][128][SST];

    const int tid = threadIdx.x;
    const int lane = tid & 31, wid = tid >> 5;
    const int wm = wid >> 2, wn = wid & 3;
    const int gid = lane >> 2, tig = lane & 3;
    const int m0 = blockIdx.y * 128, n0 = blockIdx.x * 128;

    float c[4][4][4];
    #pragma unroll
    for (int i = 0; i < 4; i++)
        #pragma unroll
        for (int j = 0; j < 4; j++)
            #pragma unroll
            for (int r = 0; r < 4; r++) c[i][j][r] = 0.f;

    const int r0l = tid >> 2,   q0l = tid & 3;
    const int r1l = r0l + 64,   q1l = q0l;

    uint4 a0v, a1v, b0v, b1v;
    a0v = *(const uint4*)&A[(size_t)(m0 + r0l) * K + q0l * 8];
    a1v = *(const uint4*)&A[(size_t)(m0 + r1l) * K + q1l * 8];
    b0v = *(const uint4*)&B[(size_t)(n0 + r0l) * K + q0l * 8];
    b1v = *(const uint4*)&B[(size_t)(n0 + r1l) * K + q1l * 8];
    *(uint4*)&As[0][r0l][q0l * 4] = a0v;
    *(uint4*)&As[0][r1l][q1l * 4] = a1v;
    *(uint4*)&Bs[0][r0l][q0l * 4] = b0v;
    *(uint4*)&Bs[0][r1l][q1l * 4] = b1v;
    __syncthreads();

    const int nk = K >> 5;
    for (int kt = 0; kt < nk; kt++) {
        const int cur = kt & 1;
        if (kt + 1 < nk) {
            const size_t kb = (size_t)(kt + 1) * 32;
            a0v = *(const uint4*)&A[(size_t)(m0 + r0l) * K + kb + q0l * 8];
            a1v = *(const uint4*)&A[(size_t)(m0 + r1l) * K + kb + q1l * 8];
            b0v = *(const uint4*)&B[(size_t)(n0 + r0l) * K + kb + q0l * 8];
            b1v = *(const uint4*)&B[(size_t)(n0 + r1l) * K + kb + q1l * 8];
        }

        #pragma unroll
        for (int kk = 0; kk < 2; kk++) {
            const int base = kk * 8;
            unsigned af[4][4], bf[4][2];
            #pragma unroll
            for (int mt = 0; mt < 4; mt++) {
                int rb = wm * 64 + mt * 16;
                af[mt][0] = As[cur][rb + gid    ][base + tig    ];
                af[mt][1] = As[cur][rb + gid + 8][base + tig    ];
                af[mt][2] = As[cur][rb + gid    ][base + tig + 4];
                af[mt][3] = As[cur][rb + gid + 8][base + tig + 4];
            }
            #pragma unroll
            for (int nt = 0; nt < 4; nt++) {
                int nb = wn * 32 + nt * 8;
                bf[nt][0] = Bs[cur][nb + gid][base + tig    ];
                bf[nt][1] = Bs[cur][nb + gid][base + tig + 4];
            }
            #pragma unroll
            for (int mt = 0; mt < 4; mt++)
                #pragma unroll
                for (int nt = 0; nt < 4; nt++)
                    mma_f16(c[mt][nt], af[mt], bf[nt]);
        }

        if (kt + 1 < nk) {
            const int nxt = (kt + 1) & 1;
            *(uint4*)&As[nxt][r0l][q0l * 4] = a0v;
            *(uint4*)&As[nxt][r1l][q1l * 4] = a1v;
            *(uint4*)&Bs[nxt][r0l][q0l * 4] = b0v;
            *(uint4*)&Bs[nxt][r1l][q1l * 4] = b1v;
            __syncthreads();
        }
    }

    #pragma unroll
    for (int mt = 0; mt < 4; mt++) {
        #pragma unroll
        for (int nt = 0; nt < 4; nt++) {
            int r0 = m0 + wm * 64 + mt * 16 + gid;
            int r1 = r0 + 8;
            int cb = n0 + wn * 32 + nt * 8 + 2 * tig;
            float bs0 = bias[cb], bs1 = bias[cb + 1];
            float v00 = c[mt][nt][0] + bs0, v01 = c[mt][nt][1] + bs1;
            float v10 = c[mt][nt][2] + bs0, v11 = c[mt][nt][3] + bs1;

            if (EPI == 0) {
                if (cb < 256) { v00 *= SCALE; v01 *= SCALE; v10 *= SCALE; v11 *= SCALE; }
                *(__half2*)&Ch[(size_t)r0 * Nn + cb] = __floats2half2_rn(v00, v01);
                *(__half2*)&Ch[(size_t)r1 * Nn + cb] = __floats2half2_rn(v10, v11);
            } else if (EPI == 1) {
                const float kk = 0.70710678118654752f;
                v00 = 0.5f * v00 * (1.f + erff(v00 * kk));
                v01 = 0.5f * v01 * (1.f + erff(v01 * kk));
                v10 = 0.5f * v10 * (1.f + erff(v10 * kk));
                v11 = 0.5f * v11 * (1.f + erff(v11 * kk));
                *(__half2*)&Ch[(size_t)r0 * Nn + cb] = __floats2half2_rn(v00, v01);
                *(__half2*)&Ch[(size_t)r1 * Nn + cb] = __floats2half2_rn(v10, v11);
            } else if (EPI == 2) {
                #pragma unroll
                for (int rr = 0; rr < 2; rr++) {
                    int m = rr ? r1 : r0;
                    float va = rr ? v10 : v00, vb = rr ? v11 : v01;
                    int bw = m / NTOK, t = m % NTOK;
                    int b = bw >> 6, w = bw & 63;
                    int wh = w >> 3, ww = w & 7;
                    int r = t / 7, cc = t % 7;
                    int gh = wh * 7 + r + SHIFT; if (gh >= HW) gh -= HW;
                    int gw = ww * 7 + cc + SHIFT; if (gw >= HW) gw -= HW;
                    size_t dst = (size_t)(b * (HW*HW) + gh * HW + gw) * DIM + cb;
                    float2 rv = *(const float2*)&res[dst];
                    *(float2*)&Cf[dst] = make_float2(va + rv.x, vb + rv.y);
                }
            } else {
                size_t d0 = (size_t)r0 * Nn + cb, d1 = (size_t)r1 * Nn + cb;
                float2 ra = *(const float2*)&res[d0];
                float2 rb2 = *(const float2*)&res[d1];
                *(float2*)&Cf[d0] = make_float2(v00 + ra.x, v01 + ra.y);
                *(float2*)&Cf[d1] = make_float2(v10 + rb2.x, v11 + rb2.y);
            }
        }
    }
}

// ---------------- tensor-core attention ----------------
// One block per (window, head). QK^T and PV via m16n8k16 HMMA.
// sQ [64][40]h, sK [56][40]h : 80B row stride, conflict-free fragment loads.
// sVT[32][72]h (V transposed, zero-padded cols), sP [64][72]h (zeroed pad),
// sS [64][60]f scores.
__global__ void __launch_bounds__(256) attn_kernel(
    const __half* __restrict__ qkv, const float* __restrict__ bias,
    __half* __restrict__ out)
{
    __shared__ __half sQ [64][40];
    __shared__ __half sK [56][40];
    __shared__ __half sVT[32][72];
    __shared__ __half sP [64][72];
    __shared__ float  sS [64][60];
    __shared__ int    regn[NTOK];

    const int bw = blockIdx.x >> 3;
    const int h  = blockIdx.x & 7;
    const int tid = threadIdx.x, lane = tid & 31, wid = tid >> 5;
    const int gid = lane >> 2, tig = lane & 3;

    // zero P (all) and VT (all): padding must be exact zeros
    for (int i = tid; i < 64 * 36; i += 256) ((uint32_t*)sP)[i] = 0;
    for (int i = tid; i < 32 * 36; i += 256) ((uint32_t*)sVT)[i] = 0;

    if (tid < NTOK) {
        int w = bw & 63;
        int wh = w >> 3, ww = w & 7;
        int r = tid / 7, c = tid % 7;
        int gh = wh * 7 + r, gw = ww * 7 + c;
        int rh = (gh < HW - WS) ? 0 : ((gh < HW - SHIFT) ? 1 : 2);
        int rw = (gw < HW - WS) ? 0 : ((gw < HW - SHIFT) ? 1 : 2);
        regn[tid] = rh * 3 + rw;
    }
    // load q,k (row-major) and v (transposed)
    for (int i = tid; i < NTOK * 4; i += 256) {
        int n = i >> 2, d8 = (i & 3) * 8;
        size_t basep = (size_t)(bw * NTOK + n) * 768 + h * HD + d8;
        uint4 qu = *(const uint4*)&qkv[basep];
        uint4 ku = *(const uint4*)&qkv[basep + 256];
        uint4 vu = *(const uint4*)&qkv[basep + 512];
        *(uint4*)&sQ[n][d8] = qu;
        *(uint4*)&sK[n][d8] = ku;
        const __half* vh = (const __half*)&vu;
        #pragma unroll
        for (int j = 0; j < 8; j++) sVT[d8 + j][n] = vh[j];
    }
    __syncthreads();

    // ---- QK^T: 28 tiles (mt 0..3, nt 0..6), warp-strided ----
    for (int t = wid; t < 28; t += 8) {
        int mt = t & 3, nt = t >> 2;
        int rb = mt * 16, nb = nt * 8;
        float c[4] = {0.f, 0.f, 0.f, 0.f};
        const uint32_t* qr0 = (const uint32_t*)&sQ[rb + gid][0];
        const uint32_t* qr1 = (const uint32_t*)&sQ[rb + gid + 8][0];
        const uint32_t* kr  = (const uint32_t*)&sK[nb + gid][0];
        #pragma unroll
        for (int ks = 0; ks < 2; ks++) {
            unsigned a[4] = { qr0[8*ks + tig], qr1[8*ks + tig],
                              qr0[8*ks + tig + 4], qr1[8*ks + tig + 4] };
            unsigned b[2] = { kr[8*ks + tig], kr[8*ks + tig + 4] };
            mma_f16(c, a, b);
        }
        sS[rb + gid    ][nb + 2*tig]     = c[0];
        sS[rb + gid    ][nb + 2*tig + 1] = c[1];
        sS[rb + gid + 8][nb + 2*tig]     = c[2];
        sS[rb + gid + 8][nb + 2*tig + 1] = c[3];
    }
    __syncthreads();

    // ---- softmax (warp per row) ----
    const float* brow = bias + h * (NTOK * NTOK);
    bool has1 = lane < (NTOK - 32);
    int m1c = has1 ? lane + 32 : lane;

    for (int n = wid; n < NTOK; n += 8) {
        int rn = regn[n];
        float a0 = sS[n][lane] + brow[n * NTOK + lane]
                 + ((rn != regn[lane]) ? -100.f : 0.f);
        float a1 = has1 ? (sS[n][m1c] + brow[n * NTOK + m1c]
                 + ((rn != regn[m1c]) ? -100.f : 0.f)) : -1e30f;

        float mx = fmaxf(a0, a1);
        #pragma unroll
        for (int o = 16; o > 0; o >>= 1) mx = fmaxf(mx, __shfl_xor_sync(0xFFFFFFFFu, mx, o));
        float e0 = __expf(a0 - mx);
        float e1 = has1 ? __expf(a1 - mx) : 0.f;
        float sm = e0 + e1;
        #pragma unroll
        for (int o = 16; o > 0; o >>= 1) sm += __shfl_xor_sync(0xFFFFFFFFu, sm, o);
        float inv = 1.f / sm;
        sP[n][lane] = __float2half(e0 * inv);
        if (has1) sP[n][m1c] = __float2half(e1 * inv);
    }
    __syncthreads();

    // ---- PV: 16 tiles (mt 0..3, nt 0..3), 2 per warp ----
    for (int t = wid; t < 16; t += 8) {
        int mt = t & 3, nt = t >> 2;
        int rb = mt * 16, nb = nt * 8;
        float c[4] = {0.f, 0.f, 0.f, 0.f};
        const uint32_t* pr0 = (const uint32_t*)&sP[rb + gid][0];
        const uint32_t* pr1 = (const uint32_t*)&sP[rb + gid + 8][0];
        const uint32_t* vr  = (const uint32_t*)&sVT[nb + gid][0];
        #pragma unroll
        for (int ks = 0; ks < 4; ks++) {
            unsigned a[4] = { pr0[8*ks + tig], pr1[8*ks + tig],
                              pr0[8*ks + tig + 4], pr1[8*ks + tig + 4] };
            unsigned b[2] = { vr[8*ks + tig], vr[8*ks + tig + 4] };
            mma_f16(c, a, b);
        }
        int n0 = rb + gid, n1 = n0 + 8;
        int d = nb + 2 * tig;
        if (n0 < NTOK)
            *(__half2*)&out[(size_t)(bw * NTOK + n0) * 256 + h * HD + d] =
                __floats2half2_rn(c[0], c[1]);
        if (n1 < NTOK)
            *(__half2*)&out[(size_t)(bw * NTOK + n1) * 256 + h * HD + d] =
                __floats2half2_rn(c[2], c[3]);
    }
}

// ---------------- launcher ----------------
extern "C" void kernel_launch(void* const* d_in, const int* in_sizes, int n_in,
                              void* d_out, int out_size)
{
    (void)in_sizes; (void)n_in; (void)out_size;
    const float* x        = (const float*)d_in[0];
    const float* norm1_g  = (const float*)d_in[1];
    const float* norm1_b  = (const float*)d_in[2];
    const float* qkv_w    = (const float*)d_in[3];
    const float* qkv_b    = (const float*)d_in[4];
    const float* rel_tab  = (const float*)d_in[5];
    const float* proj_w   = (const float*)d_in[6];
    const float* proj_b   = (const float*)d_in[7];
    const float* norm2_g  = (const float*)d_in[8];
    const float* norm2_b  = (const float*)d_in[9];
    const float* fc1_w    = (const float*)d_in[10];
    const float* fc1_b    = (const float*)d_in[11];
    const float* fc2_w    = (const float*)d_in[12];
    const float* fc2_b    = (const float*)d_in[13];
    float* out = (float*)d_out;

    __half *p_a, *p_qkv, *p_h1, *p_wqkv, *p_wproj, *p_wfc1, *p_wfc2;
    float *p_xres, *p_bias;
    cudaGetSymbolAddress((void**)&p_a,     hb_a);
    cudaGetSymbolAddress((void**)&p_qkv,   hb_qkv);
    cudaGetSymbolAddress((void**)&p_h1,    hb_h1);
    cudaGetSymbolAddress((void**)&p_xres,  g_xres);
    cudaGetSymbolAddress((void**)&p_bias,  g_bias);
    cudaGetSymbolAddress((void**)&p_wqkv,  hw_qkv);
    cudaGetSymbolAddress((void**)&p_wproj, hw_proj);
    cudaGetSymbolAddress((void**)&p_wfc1,  hw_fc1);
    cudaGetSymbolAddress((void**)&p_wfc2,  hw_fc2);

    const int M = MTOK;

    bias_kernel<<<(NH*NTOK*NTOK + 255)/256, 256>>>(rel_tab, p_bias);
    wconv_kernel<<<(768*256 + 255)/256, 256>>>(qkv_w, p_wqkv, 768*256);
    wconv_kernel<<<(256*256 + 255)/256, 256>>>(proj_w, p_wproj, 256*256);
    wconv_kernel<<<(1024*256 + 255)/256, 256>>>(fc1_w, p_wfc1, 1024*256);
    wconv_kernel<<<(256*1024 + 255)/256, 256>>>(fc2_w, p_wfc2, 256*1024);

    ln_kernel<1><<<M, 256>>>(x, p_a, norm1_g, norm1_b);
    hgemm<0><<<dim3(768/128, M/128), 256>>>(p_a, p_wqkv, qkv_b, nullptr, p_qkv, nullptr, M, 768, 256);
    attn_kernel<<<BW * NH, 256>>>(p_qkv, p_bias, p_a);
    hgemm<2><<<dim3(256/128, M/128), 256>>>(p_a, p_wproj, proj_b, p_xres, nullptr, x, M, 256, 256);
    ln_kernel<0><<<M, 256>>>(p_xres, p_a, norm2_g, norm2_b);
    hgemm<1><<<dim3(1024/128, M/128), 256>>>(p_a, p_wfc1, fc1_b, nullptr, p_h1, nullptr, M, 1024, 256);
    hgemm<3><<<dim3(256/128, M/128), 256>>>(p_h1, p_wfc2, fc2_b, out, nullptr, p_xres, M, 256, 1024);
}

// round 7
// speedup vs baseline: 2.3103x; 1.0696x over previous
#include <cuda_runtime.h>
#include <cuda_fp16.h>
#include <math.h>
#include <stdint.h>

// ---------------- problem constants ----------------
#define BATCH   32
#define HW      56
#define DIM     256
#define WS      7
#define SHIFT   3
#define NH      8
#define HD      32
#define NTOK    49
#define NWIN    64
#define BW      (BATCH*NWIN)
#define MTOK    (BATCH*HW*HW)   // 100352
#define SCALE   0.17677669529663687f

// ---------------- scratch ----------------
__device__ __half hb_a  [(size_t)MTOK * 256];
__device__ __half hb_qkv[(size_t)MTOK * 768];
__device__ __half hb_h1 [(size_t)MTOK * 1024];
__device__ float  g_xres[(size_t)MTOK * 256];
__device__ float  g_bias[NH * NTOK * NTOK];
__device__ __half hw_qkv [768 * 256];
__device__ __half hw_proj[256 * 256];
__device__ __half hw_fc1 [1024 * 256];
__device__ __half hw_fc2 [256 * 1024];

// ---------------- PTX helpers ----------------
__device__ __forceinline__ uint32_t cvta_s(const void* p) {
    uint32_t a;
    asm("{ .reg .u64 t; cvta.to.shared.u64 t, %1; cvt.u32.u64 %0, t; }" : "=r"(a) : "l"(p));
    return a;
}
__device__ __forceinline__ void ldsm_x4(unsigned* r, uint32_t a) {
    asm volatile("ldmatrix.sync.aligned.m8n8.x4.shared.b16 {%0,%1,%2,%3}, [%4];"
        : "=r"(r[0]), "=r"(r[1]), "=r"(r[2]), "=r"(r[3]) : "r"(a));
}
__device__ __forceinline__ void ldsm_x2(unsigned* r, uint32_t a) {
    asm volatile("ldmatrix.sync.aligned.m8n8.x2.shared.b16 {%0,%1}, [%2];"
        : "=r"(r[0]), "=r"(r[1]) : "r"(a));
}
#define CP_ASYNC16(dst, src) asm volatile("cp.async.ca.shared.global [%0], [%1], 16;" :: "r"(dst), "l"(src))
#define CP_COMMIT()          asm volatile("cp.async.commit_group;" ::: "memory")
#define CP_WAIT1()           asm volatile("cp.async.wait_group 1;" ::: "memory")
#define CP_WAIT0()           asm volatile("cp.async.wait_group 0;" ::: "memory")

__device__ __forceinline__ void mma_f16(float* c, const unsigned* a, const unsigned* b) {
    asm("mma.sync.aligned.m16n8k16.row.col.f32.f16.f16.f32 "
        "{%0,%1,%2,%3},{%4,%5,%6,%7},{%8,%9},{%0,%1,%2,%3};"
        : "+f"(c[0]), "+f"(c[1]), "+f"(c[2]), "+f"(c[3])
        : "r"(a[0]), "r"(a[1]), "r"(a[2]), "r"(a[3]), "r"(b[0]), "r"(b[1]));
}

// ---------------- weight fp32 -> fp16 ----------------
__global__ void wconv_kernel(const float* __restrict__ w, __half* __restrict__ o, int n)
{
    int i = blockIdx.x * 256 + threadIdx.x;
    if (i < n) o[i] = __float2half(w[i]);
}

// ---------------- rel-pos bias ----------------
__global__ void bias_kernel(const float* __restrict__ rel_table, float* __restrict__ bias)
{
    int i = blockIdx.x * 256 + threadIdx.x;
    if (i >= NH * NTOK * NTOK) return;
    int h = i / (NTOK*NTOK), rem = i % (NTOK*NTOK);
    int n = rem / NTOK, m = rem % NTOK;
    int rn = n / 7, cn = n % 7, rm = m / 7, cm = m % 7;
    int idx = (rn - rm + 6) * 13 + (cn - cm + 6);
    bias[i] = rel_table[idx * NH + h];
}

// ---------------- LayerNorm (fp32 in, fp16 out) ----------------
template<int PERM>
__global__ void __launch_bounds__(256) ln_kernel(
    const float* __restrict__ in, __half* __restrict__ out,
    const float* __restrict__ gam, const float* __restrict__ bet)
{
    int row = blockIdx.x;
    int src;
    if (PERM) {
        int bw = row / NTOK, t = row % NTOK;
        int b = bw >> 6, w = bw & 63;
        int wh = w >> 3, ww = w & 7;
        int r = t / 7, c = t % 7;
        int gh = wh * 7 + r + SHIFT; if (gh >= HW) gh -= HW;
        int gw = ww * 7 + c + SHIFT; if (gw >= HW) gw -= HW;
        src = (b * (HW*HW) + gh * HW + gw) * DIM;
    } else {
        src = row * DIM;
    }
    int dst = row * DIM;
    int tid = threadIdx.x;
    float val = in[src + tid];

    float s = val, q = val * val;
    #pragma unroll
    for (int o = 16; o > 0; o >>= 1) {
        s += __shfl_down_sync(0xFFFFFFFFu, s, o);
        q += __shfl_down_sync(0xFFFFFFFFu, q, o);
    }
    __shared__ float rs[8], rq[8];
    __shared__ float smu, srstd;
    int wid = tid >> 5, lane = tid & 31;
    if (lane == 0) { rs[wid] = s; rq[wid] = q; }
    __syncthreads();
    if (tid == 0) {
        float S = 0.f, Q = 0.f;
        #pragma unroll
        for (int i = 0; i < 8; i++) { S += rs[i]; Q += rq[i]; }
        float mu = S * (1.0f/DIM);
        smu = mu;
        srstd = rsqrtf(Q * (1.0f/DIM) - mu*mu + 1e-5f);
    }
    __syncthreads();
    out[dst + tid] = __float2half((val - smu) * srstd * gam[tid] + bet[tid]);
}

// ---------------- fp16 GEMM: cp.async 3-stage + ldmatrix ----------------
// C[M,N] = A[M,K] @ B[N,K]^T + bias. Block 128x128, BK=32 halves, 3 stages.
// Stage layout: 128 rows x 40 halves (80B stride, ldmatrix conflict-free).
#define STG_H    (128 * 40)           // halves per operand stage
#define STG_B    (STG_H * 2)          // bytes  (10240)
#define GSMEM    (6 * STG_B)          // 3 stages x (A + B) = 61440 B

template<int EPI>
__global__ void __launch_bounds__(256, 2) hgemm(
    const __half* __restrict__ A, const __half* __restrict__ B,
    const float* __restrict__ bias, float* __restrict__ Cf, __half* __restrict__ Ch,
    const float* __restrict__ res, int M, int Nn, int K)
{
    extern __shared__ __half dsm[];

    const int tid = threadIdx.x;
    const int lane = tid & 31, wid = tid >> 5;
    const int wm = wid >> 2, wn = wid & 3;
    const int gid = lane >> 2, tig = lane & 3;
    const int m0 = blockIdx.y * 128, n0 = blockIdx.x * 128;

    const uint32_t sbase = cvta_s(dsm);
    const uint32_t sA = sbase;
    const uint32_t sB = sbase + 3 * STG_B;

    // loader slots: slot = tid (+256): row = slot>>2 (0..127), q = slot&3
    const int lr0 = tid >> 2, lq0 = (tid & 3);
    const int lr1 = lr0 + 64;

    float c[4][4][4];
    #pragma unroll
    for (int i = 0; i < 4; i++)
        #pragma unroll
        for (int j = 0; j < 4; j++)
            #pragma unroll
            for (int r = 0; r < 4; r++) c[i][j][r] = 0.f;

    const int nk = K >> 5;

    // ldmatrix per-lane address components (byte offsets within a stage)
    // A: row = wm*64 + mt*16 + (lane&15), col halves = kk*16 + (lane>>4)*8
    const uint32_t a_off = ((uint32_t)(wm * 64 + (lane & 15)) * 40 + (lane >> 4) * 8) * 2;
    // B: row = wn*32 + nt*8 + (lane&7),  col halves = kk*16 + ((lane>>3)&1)*8
    const uint32_t b_off = ((uint32_t)(wn * 32 + (lane & 7)) * 40 + ((lane >> 3) & 1) * 8) * 2;

    // ---- async loader for one chunk ----
    auto issue = [&](int kt, int stg) {
        const size_t kb = (size_t)kt * 32 + lq0 * 8;
        uint32_t dA0 = sA + stg * STG_B + (lr0 * 40 + lq0 * 8) * 2;
        uint32_t dA1 = sA + stg * STG_B + (lr1 * 40 + lq0 * 8) * 2;
        uint32_t dB0 = sB + stg * STG_B + (lr0 * 40 + lq0 * 8) * 2;
        uint32_t dB1 = sB + stg * STG_B + (lr1 * 40 + lq0 * 8) * 2;
        CP_ASYNC16(dA0, &A[(size_t)(m0 + lr0) * K + kb]);
        CP_ASYNC16(dA1, &A[(size_t)(m0 + lr1) * K + kb]);
        CP_ASYNC16(dB0, &B[(size_t)(n0 + lr0) * K + kb]);
        CP_ASYNC16(dB1, &B[(size_t)(n0 + lr1) * K + kb]);
        CP_COMMIT();
    };

    issue(0, 0);
    issue(1, 1);

    for (int kt = 0; kt < nk; kt++) {
        const int stg = kt % 3;
        if (kt + 2 < nk) { CP_WAIT1(); } else { CP_WAIT0(); }
        __syncthreads();

        const uint32_t aS = sA + stg * STG_B + a_off;
        const uint32_t bS = sB + stg * STG_B + b_off;
        #pragma unroll
        for (int kk = 0; kk < 2; kk++) {
            unsigned af[4][4], bf[4][2];
            #pragma unroll
            for (int mt = 0; mt < 4; mt++)
                ldsm_x4(af[mt], aS + (mt * 16 * 40 + kk * 16) * 2);
            #pragma unroll
            for (int nt = 0; nt < 4; nt++)
                ldsm_x2(bf[nt], bS + (nt * 8 * 40 + kk * 16) * 2);
            #pragma unroll
            for (int mt = 0; mt < 4; mt++)
                #pragma unroll
                for (int nt = 0; nt < 4; nt++)
                    mma_f16(c[mt][nt], af[mt], bf[nt]);
        }
        __syncthreads();
        if (kt + 2 < nk) issue(kt + 2, (kt + 2) % 3);
    }

    // ---------------- epilogue ----------------
    #pragma unroll
    for (int mt = 0; mt < 4; mt++) {
        #pragma unroll
        for (int nt = 0; nt < 4; nt++) {
            int r0 = m0 + wm * 64 + mt * 16 + gid;
            int r1 = r0 + 8;
            int cb = n0 + wn * 32 + nt * 8 + 2 * tig;
            float bs0 = bias[cb], bs1 = bias[cb + 1];
            float v00 = c[mt][nt][0] + bs0, v01 = c[mt][nt][1] + bs1;
            float v10 = c[mt][nt][2] + bs0, v11 = c[mt][nt][3] + bs1;

            if (EPI == 0) {
                if (cb < 256) { v00 *= SCALE; v01 *= SCALE; v10 *= SCALE; v11 *= SCALE; }
                *(__half2*)&Ch[(size_t)r0 * Nn + cb] = __floats2half2_rn(v00, v01);
                *(__half2*)&Ch[(size_t)r1 * Nn + cb] = __floats2half2_rn(v10, v11);
            } else if (EPI == 1) {
                const float kk = 0.70710678118654752f;
                v00 = 0.5f * v00 * (1.f + erff(v00 * kk));
                v01 = 0.5f * v01 * (1.f + erff(v01 * kk));
                v10 = 0.5f * v10 * (1.f + erff(v10 * kk));
                v11 = 0.5f * v11 * (1.f + erff(v11 * kk));
                *(__half2*)&Ch[(size_t)r0 * Nn + cb] = __floats2half2_rn(v00, v01);
                *(__half2*)&Ch[(size_t)r1 * Nn + cb] = __floats2half2_rn(v10, v11);
            } else if (EPI == 2) {
                #pragma unroll
                for (int rr = 0; rr < 2; rr++) {
                    int m = rr ? r1 : r0;
                    float va = rr ? v10 : v00, vb = rr ? v11 : v01;
                    int bw = m / NTOK, t = m % NTOK;
                    int b = bw >> 6, w = bw & 63;
                    int wh = w >> 3, ww = w & 7;
                    int r = t / 7, cc = t % 7;
                    int gh = wh * 7 + r + SHIFT; if (gh >= HW) gh -= HW;
                    int gw = ww * 7 + cc + SHIFT; if (gw >= HW) gw -= HW;
                    size_t dst = (size_t)(b * (HW*HW) + gh * HW + gw) * DIM + cb;
                    float2 rv = *(const float2*)&res[dst];
                    *(float2*)&Cf[dst] = make_float2(va + rv.x, vb + rv.y);
                }
            } else {
                size_t d0 = (size_t)r0 * Nn + cb, d1 = (size_t)r1 * Nn + cb;
                float2 ra = *(const float2*)&res[d0];
                float2 rb2 = *(const float2*)&res[d1];
                *(float2*)&Cf[d0] = make_float2(v00 + ra.x, v01 + ra.y);
                *(float2*)&Cf[d1] = make_float2(v10 + rb2.x, v11 + rb2.y);
            }
        }
    }
}

// ---------------- tensor-core attention (unchanged from R6) ----------------
__global__ void __launch_bounds__(256) attn_kernel(
    const __half* __restrict__ qkv, const float* __restrict__ bias,
    __half* __restrict__ out)
{
    __shared__ __half sQ [64][40];
    __shared__ __half sK [56][40];
    __shared__ __half sVT[32][72];
    __shared__ __half sP [64][72];
    __shared__ float  sS [64][60];
    __shared__ int    regn[NTOK];

    const int bw = blockIdx.x >> 3;
    const int h  = blockIdx.x & 7;
    const int tid = threadIdx.x, lane = tid & 31, wid = tid >> 5;
    const int gid = lane >> 2, tig = lane & 3;

    for (int i = tid; i < 64 * 36; i += 256) ((uint32_t*)sP)[i] = 0;
    for (int i = tid; i < 32 * 36; i += 256) ((uint32_t*)sVT)[i] = 0;

    if (tid < NTOK) {
        int w = bw & 63;
        int wh = w >> 3, ww = w & 7;
        int r = tid / 7, c = tid % 7;
        int gh = wh * 7 + r, gw = ww * 7 + c;
        int rh = (gh < HW - WS) ? 0 : ((gh < HW - SHIFT) ? 1 : 2);
        int rw = (gw < HW - WS) ? 0 : ((gw < HW - SHIFT) ? 1 : 2);
        regn[tid] = rh * 3 + rw;
    }
    for (int i = tid; i < NTOK * 4; i += 256) {
        int n = i >> 2, d8 = (i & 3) * 8;
        size_t basep = (size_t)(bw * NTOK + n) * 768 + h * HD + d8;
        uint4 qu = *(const uint4*)&qkv[basep];
        uint4 ku = *(const uint4*)&qkv[basep + 256];
        uint4 vu = *(const uint4*)&qkv[basep + 512];
        *(uint4*)&sQ[n][d8] = qu;
        *(uint4*)&sK[n][d8] = ku;
        const __half* vh = (const __half*)&vu;
        #pragma unroll
        for (int j = 0; j < 8; j++) sVT[d8 + j][n] = vh[j];
    }
    __syncthreads();

    for (int t = wid; t < 28; t += 8) {
        int mt = t & 3, nt = t >> 2;
        int rb = mt * 16, nb = nt * 8;
        float c[4] = {0.f, 0.f, 0.f, 0.f};
        const uint32_t* qr0 = (const uint32_t*)&sQ[rb + gid][0];
        const uint32_t* qr1 = (const uint32_t*)&sQ[rb + gid + 8][0];
        const uint32_t* kr  = (const uint32_t*)&sK[nb + gid][0];
        #pragma unroll
        for (int ks = 0; ks < 2; ks++) {
            unsigned a[4] = { qr0[8*ks + tig], qr1[8*ks + tig],
                              qr0[8*ks + tig + 4], qr1[8*ks + tig + 4] };
            unsigned b[2] = { kr[8*ks + tig], kr[8*ks + tig + 4] };
            mma_f16(c, a, b);
        }
        sS[rb + gid    ][nb + 2*tig]     = c[0];
        sS[rb + gid    ][nb + 2*tig + 1] = c[1];
        sS[rb + gid + 8][nb + 2*tig]     = c[2];
        sS[rb + gid + 8][nb + 2*tig + 1] = c[3];
    }
    __syncthreads();

    const float* brow = bias + h * (NTOK * NTOK);
    bool has1 = lane < (NTOK - 32);
    int m1c = has1 ? lane + 32 : lane;

    for (int n = wid; n < NTOK; n += 8) {
        int rn = regn[n];
        float a0 = sS[n][lane] + brow[n * NTOK + lane]
                 + ((rn != regn[lane]) ? -100.f : 0.f);
        float a1 = has1 ? (sS[n][m1c] + brow[n * NTOK + m1c]
                 + ((rn != regn[m1c]) ? -100.f : 0.f)) : -1e30f;

        float mx = fmaxf(a0, a1);
        #pragma unroll
        for (int o = 16; o > 0; o >>= 1) mx = fmaxf(mx, __shfl_xor_sync(0xFFFFFFFFu, mx, o));
        float e0 = __expf(a0 - mx);
        float e1 = has1 ? __expf(a1 - mx) : 0.f;
        float sm = e0 + e1;
        #pragma unroll
        for (int o = 16; o > 0; o >>= 1) sm += __shfl_xor_sync(0xFFFFFFFFu, sm, o);
        float inv = 1.f / sm;
        sP[n][lane] = __float2half(e0 * inv);
        if (has1) sP[n][m1c] = __float2half(e1 * inv);
    }
    __syncthreads();

    for (int t = wid; t < 16; t += 8) {
        int mt = t & 3, nt = t >> 2;
        int rb = mt * 16, nb = nt * 8;
        float c[4] = {0.f, 0.f, 0.f, 0.f};
        const uint32_t* pr0 = (const uint32_t*)&sP[rb + gid][0];
        const uint32_t* pr1 = (const uint32_t*)&sP[rb + gid + 8][0];
        const uint32_t* vr  = (const uint32_t*)&sVT[nb + gid][0];
        #pragma unroll
        for (int ks = 0; ks < 4; ks++) {
            unsigned a[4] = { pr0[8*ks + tig], pr1[8*ks + tig],
                              pr0[8*ks + tig + 4], pr1[8*ks + tig + 4] };
            unsigned b[2] = { vr[8*ks + tig], vr[8*ks + tig + 4] };
            mma_f16(c, a, b);
        }
        int n0 = rb + gid, n1 = n0 + 8;
        int d = nb + 2 * tig;
        if (n0 < NTOK)
            *(__half2*)&out[(size_t)(bw * NTOK + n0) * 256 + h * HD + d] =
                __floats2half2_rn(c[0], c[1]);
        if (n1 < NTOK)
            *(__half2*)&out[(size_t)(bw * NTOK + n1) * 256 + h * HD + d] =
                __floats2half2_rn(c[2], c[3]);
    }
}

// ---------------- launcher ----------------
extern "C" void kernel_launch(void* const* d_in, const int* in_sizes, int n_in,
                              void* d_out, int out_size)
{
    (void)in_sizes; (void)n_in; (void)out_size;
    const float* x        = (const float*)d_in[0];
    const float* norm1_g  = (const float*)d_in[1];
    const float* norm1_b  = (const float*)d_in[2];
    const float* qkv_w    = (const float*)d_in[3];
    const float* qkv_b    = (const float*)d_in[4];
    const float* rel_tab  = (const float*)d_in[5];
    const float* proj_w   = (const float*)d_in[6];
    const float* proj_b   = (const float*)d_in[7];
    const float* norm2_g  = (const float*)d_in[8];
    const float* norm2_b  = (const float*)d_in[9];
    const float* fc1_w    = (const float*)d_in[10];
    const float* fc1_b    = (const float*)d_in[11];
    const float* fc2_w    = (const float*)d_in[12];
    const float* fc2_b    = (const float*)d_in[13];
    float* out = (float*)d_out;

    __half *p_a, *p_qkv, *p_h1, *p_wqkv, *p_wproj, *p_wfc1, *p_wfc2;
    float *p_xres, *p_bias;
    cudaGetSymbolAddress((void**)&p_a,     hb_a);
    cudaGetSymbolAddress((void**)&p_qkv,   hb_qkv);
    cudaGetSymbolAddress((void**)&p_h1,    hb_h1);
    cudaGetSymbolAddress((void**)&p_xres,  g_xres);
    cudaGetSymbolAddress((void**)&p_bias,  g_bias);
    cudaGetSymbolAddress((void**)&p_wqkv,  hw_qkv);
    cudaGetSymbolAddress((void**)&p_wproj, hw_proj);
    cudaGetSymbolAddress((void**)&p_wfc1,  hw_fc1);
    cudaGetSymbolAddress((void**)&p_wfc2,  hw_fc2);

    cudaFuncSetAttribute(hgemm<0>, cudaFuncAttributeMaxDynamicSharedMemorySize, GSMEM);
    cudaFuncSetAttribute(hgemm<1>, cudaFuncAttributeMaxDynamicSharedMemorySize, GSMEM);
    cudaFuncSetAttribute(hgemm<2>, cudaFuncAttributeMaxDynamicSharedMemorySize, GSMEM);
    cudaFuncSetAttribute(hgemm<3>, cudaFuncAttributeMaxDynamicSharedMemorySize, GSMEM);

    const int M = MTOK;

    bias_kernel<<<(NH*NTOK*NTOK + 255)/256, 256>>>(rel_tab, p_bias);
    wconv_kernel<<<(768*256 + 255)/256, 256>>>(qkv_w, p_wqkv, 768*256);
    wconv_kernel<<<(256*256 + 255)/256, 256>>>(proj_w, p_wproj, 256*256);
    wconv_kernel<<<(1024*256 + 255)/256, 256>>>(fc1_w, p_wfc1, 1024*256);
    wconv_kernel<<<(256*1024 + 255)/256, 256>>>(fc2_w, p_wfc2, 256*1024);

    ln_kernel<1><<<M, 256>>>(x, p_a, norm1_g, norm1_b);
    hgemm<0><<<dim3(768/128, M/128), 256, GSMEM>>>(p_a, p_wqkv, qkv_b, nullptr, p_qkv, nullptr, M, 768, 256);
    attn_kernel<<<BW * NH, 256>>>(p_qkv, p_bias, p_a);
    hgemm<2><<<dim3(256/128, M/128), 256, GSMEM>>>(p_a, p_wproj, proj_b, p_xres, nullptr, x, M, 256, 256);
    ln_kernel<0><<<M, 256>>>(p_xres, p_a, norm2_g, norm2_b);
    hgemm<1><<<dim3(1024/128, M/128), 256, GSMEM>>>(p_a, p_wfc1, fc1_b, nullptr, p_h1, nullptr, M, 1024, 256);
    hgemm<3><<<dim3(256/128, M/128), 256, GSMEM>>>(p_h1, p_wfc2, fc2_b, out, nullptr, p_xres, M, 256, 1024);
}

// round 8
// speedup vs baseline: 2.7151x; 1.1752x over previous
#include <cuda_runtime.h>
#include <cuda_fp16.h>
#include <math.h>
#include <stdint.h>

// ---------------- problem constants ----------------
#define BATCH   32
#define HW      56
#define DIM     256
#define WS      7
#define SHIFT   3
#define NH      8
#define HD      32
#define NTOK    49
#define NWIN    64
#define BW      (BATCH*NWIN)
#define MTOK    (BATCH*HW*HW)   // 100352
#define SCALE   0.17677669529663687f

// ---------------- scratch ----------------
__device__ __half hb_a  [(size_t)MTOK * 256];
__device__ __half hb_qkv[(size_t)MTOK * 768];
__device__ __half hb_h1 [(size_t)MTOK * 1024];
__device__ float  g_xres[(size_t)MTOK * 256];
__device__ float  g_bias[NH * NTOK * NTOK];
__device__ __half hw_qkv [768 * 256];
__device__ __half hw_proj[256 * 256];
__device__ __half hw_fc1 [1024 * 256];
__device__ __half hw_fc2 [256 * 1024];

// ---------------- PTX helpers ----------------
__device__ __forceinline__ uint32_t cvta_s(const void* p) {
    uint32_t a;
    asm("{ .reg .u64 t; cvta.to.shared.u64 t, %1; cvt.u32.u64 %0, t; }" : "=r"(a) : "l"(p));
    return a;
}
__device__ __forceinline__ void ldsm_x4(unsigned* r, uint32_t a) {
    asm volatile("ldmatrix.sync.aligned.m8n8.x4.shared.b16 {%0,%1,%2,%3}, [%4];"
        : "=r"(r[0]), "=r"(r[1]), "=r"(r[2]), "=r"(r[3]) : "r"(a));
}
__device__ __forceinline__ void ldsm_x2(unsigned* r, uint32_t a) {
    asm volatile("ldmatrix.sync.aligned.m8n8.x2.shared.b16 {%0,%1}, [%2];"
        : "=r"(r[0]), "=r"(r[1]) : "r"(a));
}
#define CP_ASYNC16(dst, src) asm volatile("cp.async.ca.shared.global [%0], [%1], 16;" :: "r"(dst), "l"(src))
#define CP_COMMIT()          asm volatile("cp.async.commit_group;" ::: "memory")
#define CP_WAIT1()           asm volatile("cp.async.wait_group 1;" ::: "memory")
#define CP_WAIT0()           asm volatile("cp.async.wait_group 0;" ::: "memory")

__device__ __forceinline__ void mma_f16(float* c, const unsigned* a, const unsigned* b) {
    asm("mma.sync.aligned.m16n8k16.row.col.f32.f16.f16.f32 "
        "{%0,%1,%2,%3},{%4,%5,%6,%7},{%8,%9},{%0,%1,%2,%3};"
        : "+f"(c[0]), "+f"(c[1]), "+f"(c[2]), "+f"(c[3])
        : "r"(a[0]), "r"(a[1]), "r"(a[2]), "r"(a[3]), "r"(b[0]), "r"(b[1]));
}

// ---------------- weight fp32 -> fp16 ----------------
__global__ void wconv_kernel(const float* __restrict__ w0, __half* __restrict__ o0, int n0,
                             const float* __restrict__ w1, __half* __restrict__ o1, int n1)
{
    int i = blockIdx.x * 256 + threadIdx.x;
    if (i < n0) o0[i] = __float2half(w0[i]);
    else if (i < n0 + n1) o1[i - n0] = __float2half(w1[i - n0]);
}

// ---------------- rel-pos bias ----------------
__global__ void bias_kernel(const float* __restrict__ rel_table, float* __restrict__ bias)
{
    int i = blockIdx.x * 256 + threadIdx.x;
    if (i >= NH * NTOK * NTOK) return;
    int h = i / (NTOK*NTOK), rem = i % (NTOK*NTOK);
    int n = rem / NTOK, m = rem % NTOK;
    int rn = n / 7, cn = n % 7, rm = m / 7, cm = m % 7;
    int idx = (rn - rm + 6) * 13 + (cn - cm + 6);
    bias[i] = rel_table[idx * NH + h];
}

// ---------------- LayerNorm: one row per warp, float4 I/O ----------------
template<int PERM>
__global__ void __launch_bounds__(256) ln_kernel(
    const float* __restrict__ in, __half* __restrict__ out,
    const float* __restrict__ gam, const float* __restrict__ bet)
{
    const int row = blockIdx.x * 8 + (threadIdx.x >> 5);
    const int lane = threadIdx.x & 31;
    int src;
    if (PERM) {
        int bw = row / NTOK, t = row % NTOK;
        int b = bw >> 6, w = bw & 63;
        int wh = w >> 3, ww = w & 7;
        int r = t / 7, c = t % 7;
        int gh = wh * 7 + r + SHIFT; if (gh >= HW) gh -= HW;
        int gw = ww * 7 + c + SHIFT; if (gw >= HW) gw -= HW;
        src = (b * (HW*HW) + gh * HW + gw) * DIM;
    } else {
        src = row * DIM;
    }
    const int col = lane * 8;
    float4 v0 = *(const float4*)&in[src + col];
    float4 v1 = *(const float4*)&in[src + col + 4];

    float s = v0.x+v0.y+v0.z+v0.w + v1.x+v1.y+v1.z+v1.w;
    float q = v0.x*v0.x+v0.y*v0.y+v0.z*v0.z+v0.w*v0.w
            + v1.x*v1.x+v1.y*v1.y+v1.z*v1.z+v1.w*v1.w;
    #pragma unroll
    for (int o = 16; o > 0; o >>= 1) {
        s += __shfl_xor_sync(0xFFFFFFFFu, s, o);
        q += __shfl_xor_sync(0xFFFFFFFFu, q, o);
    }
    float mu = s * (1.0f/DIM);
    float rstd = rsqrtf(q * (1.0f/DIM) - mu*mu + 1e-5f);

    float4 g0 = *(const float4*)&gam[col], g1 = *(const float4*)&gam[col+4];
    float4 b0 = *(const float4*)&bet[col], b1 = *(const float4*)&bet[col+4];

    uint4 o8;
    ((__half2*)&o8)[0] = __floats2half2_rn((v0.x-mu)*rstd*g0.x+b0.x, (v0.y-mu)*rstd*g0.y+b0.y);
    ((__half2*)&o8)[1] = __floats2half2_rn((v0.z-mu)*rstd*g0.z+b0.z, (v0.w-mu)*rstd*g0.w+b0.w);
    ((__half2*)&o8)[2] = __floats2half2_rn((v1.x-mu)*rstd*g1.x+b1.x, (v1.y-mu)*rstd*g1.y+b1.y);
    ((__half2*)&o8)[3] = __floats2half2_rn((v1.z-mu)*rstd*g1.z+b1.z, (v1.w-mu)*rstd*g1.w+b1.w);
    *(uint4*)&out[(size_t)row * DIM + col] = o8;
}

// ---------------- fp16 GEMM: cp.async 3-stage + ldmatrix, 1 sync/chunk ----
#define STG_H    (128 * 40)
#define STG_B    (STG_H * 2)
#define GSMEM    (6 * STG_B)

template<int EPI>
__global__ void __launch_bounds__(256, 2) hgemm(
    const __half* __restrict__ A, const __half* __restrict__ B,
    const float* __restrict__ bias, float* __restrict__ Cf, __half* __restrict__ Ch,
    const float* __restrict__ res, int M, int Nn, int K)
{
    extern __shared__ __half dsm[];

    const int tid = threadIdx.x;
    const int lane = tid & 31, wid = tid >> 5;
    const int wm = wid >> 2, wn = wid & 3;
    const int gid = lane >> 2, tig = lane & 3;
    const int m0 = blockIdx.y * 128, n0 = blockIdx.x * 128;

    const uint32_t sbase = cvta_s(dsm);
    const uint32_t sA = sbase;
    const uint32_t sB = sbase + 3 * STG_B;

    const int lr0 = tid >> 2, lq0 = (tid & 3);
    const int lr1 = lr0 + 64;

    float c[4][4][4];
    #pragma unroll
    for (int i = 0; i < 4; i++)
        #pragma unroll
        for (int j = 0; j < 4; j++)
            #pragma unroll
            for (int r = 0; r < 4; r++) c[i][j][r] = 0.f;

    const int nk = K >> 5;

    const uint32_t a_off = ((uint32_t)(wm * 64 + (lane & 15)) * 40 + (lane >> 4) * 8) * 2;
    const uint32_t b_off = ((uint32_t)(wn * 32 + (lane & 7)) * 40 + ((lane >> 3) & 1) * 8) * 2;

    auto issue = [&](int kt, int stg) {
        const size_t kb = (size_t)kt * 32 + lq0 * 8;
        uint32_t dA0 = sA + stg * STG_B + (lr0 * 40 + lq0 * 8) * 2;
        uint32_t dA1 = sA + stg * STG_B + (lr1 * 40 + lq0 * 8) * 2;
        uint32_t dB0 = sB + stg * STG_B + (lr0 * 40 + lq0 * 8) * 2;
        uint32_t dB1 = sB + stg * STG_B + (lr1 * 40 + lq0 * 8) * 2;
        CP_ASYNC16(dA0, &A[(size_t)(m0 + lr0) * K + kb]);
        CP_ASYNC16(dA1, &A[(size_t)(m0 + lr1) * K + kb]);
        CP_ASYNC16(dB0, &B[(size_t)(n0 + lr0) * K + kb]);
        CP_ASYNC16(dB1, &B[(size_t)(n0 + lr1) * K + kb]);
        CP_COMMIT();
    };

    issue(0, 0);
    issue(1, 1);

    for (int kt = 0; kt < nk; kt++) {
        const int stg = kt % 3;
        if (kt + 2 < nk) { CP_WAIT1(); } else { CP_WAIT0(); }
        __syncthreads();
        // issue next chunk BEFORE compute; writes stage (kt-1)%3 whose
        // readers are fenced by the sync above. Single sync per chunk.
        if (kt + 2 < nk) issue(kt + 2, (kt + 2) % 3);

        const uint32_t aS = sA + stg * STG_B + a_off;
        const uint32_t bS = sB + stg * STG_B + b_off;
        #pragma unroll
        for (int kk = 0; kk < 2; kk++) {
            unsigned af[4][4], bf[4][2];
            #pragma unroll
            for (int mt = 0; mt < 4; mt++)
                ldsm_x4(af[mt], aS + (mt * 16 * 40 + kk * 16) * 2);
            #pragma unroll
            for (int nt = 0; nt < 4; nt++)
                ldsm_x2(bf[nt], bS + (nt * 8 * 40 + kk * 16) * 2);
            #pragma unroll
            for (int mt = 0; mt < 4; mt++)
                #pragma unroll
                for (int nt = 0; nt < 4; nt++)
                    mma_f16(c[mt][nt], af[mt], bf[nt]);
        }
    }

    // ---------------- epilogue ----------------
    #pragma unroll
    for (int mt = 0; mt < 4; mt++) {
        #pragma unroll
        for (int nt = 0; nt < 4; nt++) {
            int r0 = m0 + wm * 64 + mt * 16 + gid;
            int r1 = r0 + 8;
            int cb = n0 + wn * 32 + nt * 8 + 2 * tig;
            float bs0 = bias[cb], bs1 = bias[cb + 1];
            float v00 = c[mt][nt][0] + bs0, v01 = c[mt][nt][1] + bs1;
            float v10 = c[mt][nt][2] + bs0, v11 = c[mt][nt][3] + bs1;

            if (EPI == 0) {
                if (cb < 256) { v00 *= SCALE; v01 *= SCALE; v10 *= SCALE; v11 *= SCALE; }
                *(__half2*)&Ch[(size_t)r0 * Nn + cb] = __floats2half2_rn(v00, v01);
                *(__half2*)&Ch[(size_t)r1 * Nn + cb] = __floats2half2_rn(v10, v11);
            } else if (EPI == 1) {
                const float kk = 0.70710678118654752f;
                v00 = 0.5f * v00 * (1.f + erff(v00 * kk));
                v01 = 0.5f * v01 * (1.f + erff(v01 * kk));
                v10 = 0.5f * v10 * (1.f + erff(v10 * kk));
                v11 = 0.5f * v11 * (1.f + erff(v11 * kk));
                *(__half2*)&Ch[(size_t)r0 * Nn + cb] = __floats2half2_rn(v00, v01);
                *(__half2*)&Ch[(size_t)r1 * Nn + cb] = __floats2half2_rn(v10, v11);
            } else if (EPI == 2) {
                #pragma unroll
                for (int rr = 0; rr < 2; rr++) {
                    int m = rr ? r1 : r0;
                    float va = rr ? v10 : v00, vb = rr ? v11 : v01;
                    int bw = m / NTOK, t = m % NTOK;
                    int b = bw >> 6, w = bw & 63;
                    int wh = w >> 3, ww = w & 7;
                    int r = t / 7, cc = t % 7;
                    int gh = wh * 7 + r + SHIFT; if (gh >= HW) gh -= HW;
                    int gw = ww * 7 + cc + SHIFT; if (gw >= HW) gw -= HW;
                    size_t dst = (size_t)(b * (HW*HW) + gh * HW + gw) * DIM + cb;
                    float2 rv = *(const float2*)&res[dst];
                    *(float2*)&Cf[dst] = make_float2(va + rv.x, vb + rv.y);
                }
            } else {
                size_t d0 = (size_t)r0 * Nn + cb, d1 = (size_t)r1 * Nn + cb;
                float2 ra = *(const float2*)&res[d0];
                float2 rb2 = *(const float2*)&res[d1];
                *(float2*)&Cf[d0] = make_float2(v00 + ra.x, v01 + ra.y);
                *(float2*)&Cf[d1] = make_float2(v10 + rb2.x, v11 + rb2.y);
            }
        }
    }
}

// ---------------- tensor-core attention ----------------
__global__ void __launch_bounds__(256) attn_kernel(
    const __half* __restrict__ qkv, const float* __restrict__ bias,
    __half* __restrict__ out)
{
    __shared__ __half sQ [64][40];
    __shared__ __half sK [56][40];
    __shared__ __half sVT[32][72];
    __shared__ __half sP [64][72];
    __shared__ float  sS [64][60];
    __shared__ int    regn[NTOK];

    const int bw = blockIdx.x >> 3;
    const int h  = blockIdx.x & 7;
    const int tid = threadIdx.x, lane = tid & 31, wid = tid >> 5;
    const int gid = lane >> 2, tig = lane & 3;

    for (int i = tid; i < 64 * 36; i += 256) ((uint32_t*)sP)[i] = 0;
    for (int i = tid; i < 32 * 36; i += 256) ((uint32_t*)sVT)[i] = 0;

    if (tid < NTOK) {
        int w = bw & 63;
        int wh = w >> 3, ww = w & 7;
        int r = tid / 7, c = tid % 7;
        int gh = wh * 7 + r, gw = ww * 7 + c;
        int rh = (gh < HW - WS) ? 0 : ((gh < HW - SHIFT) ? 1 : 2);
        int rw = (gw < HW - WS) ? 0 : ((gw < HW - SHIFT) ? 1 : 2);
        regn[tid] = rh * 3 + rw;
    }
    for (int i = tid; i < NTOK * 4; i += 256) {
        int n = i >> 2, d8 = (i & 3) * 8;
        size_t basep = (size_t)(bw * NTOK + n) * 768 + h * HD + d8;
        uint4 qu = *(const uint4*)&qkv[basep];
        uint4 ku = *(const uint4*)&qkv[basep + 256];
        uint4 vu = *(const uint4*)&qkv[basep + 512];
        *(uint4*)&sQ[n][d8] = qu;
        *(uint4*)&sK[n][d8] = ku;
        const __half* vh = (const __half*)&vu;
        #pragma unroll
        for (int j = 0; j < 8; j++) sVT[d8 + j][n] = vh[j];
    }
    __syncthreads();

    for (int t = wid; t < 28; t += 8) {
        int mt = t & 3, nt = t >> 2;
        int rb = mt * 16, nb = nt * 8;
        float c[4] = {0.f, 0.f, 0.f, 0.f};
        const uint32_t* qr0 = (const uint32_t*)&sQ[rb + gid][0];
        const uint32_t* qr1 = (const uint32_t*)&sQ[rb + gid + 8][0];
        const uint32_t* kr  = (const uint32_t*)&sK[nb + gid][0];
        #pragma unroll
        for (int ks = 0; ks < 2; ks++) {
            unsigned a[4] = { qr0[8*ks + tig], qr1[8*ks + tig],
                              qr0[8*ks + tig + 4], qr1[8*ks + tig + 4] };
            unsigned b[2] = { kr[8*ks + tig], kr[8*ks + tig + 4] };
            mma_f16(c, a, b);
        }
        sS[rb + gid    ][nb + 2*tig]     = c[0];
        sS[rb + gid    ][nb + 2*tig + 1] = c[1];
        sS[rb + gid + 8][nb + 2*tig]     = c[2];
        sS[rb + gid + 8][nb + 2*tig + 1] = c[3];
    }
    __syncthreads();

    const float* brow = bias + h * (NTOK * NTOK);
    bool has1 = lane < (NTOK - 32);
    int m1c = has1 ? lane + 32 : lane;

    for (int n = wid; n < NTOK; n += 8) {
        int rn = regn[n];
        float a0 = sS[n][lane] + brow[n * NTOK + lane]
                 + ((rn != regn[lane]) ? -100.f : 0.f);
        float a1 = has1 ? (sS[n][m1c] + brow[n * NTOK + m1c]
                 + ((rn != regn[m1c]) ? -100.f : 0.f)) : -1e30f;

        float mx = fmaxf(a0, a1);
        #pragma unroll
        for (int o = 16; o > 0; o >>= 1) mx = fmaxf(mx, __shfl_xor_sync(0xFFFFFFFFu, mx, o));
        float e0 = __expf(a0 - mx);
        float e1 = has1 ? __expf(a1 - mx) : 0.f;
        float sm = e0 + e1;
        #pragma unroll
        for (int o = 16; o > 0; o >>= 1) sm += __shfl_xor_sync(0xFFFFFFFFu, sm, o);
        float inv = 1.f / sm;
        sP[n][lane] = __float2half(e0 * inv);
        if (has1) sP[n][m1c] = __float2half(e1 * inv);
    }
    __syncthreads();

    for (int t = wid; t < 16; t += 8) {
        int mt = t & 3, nt = t >> 2;
        int rb = mt * 16, nb = nt * 8;
        float c[4] = {0.f, 0.f, 0.f, 0.f};
        const uint32_t* pr0 = (const uint32_t*)&sP[rb + gid][0];
        const uint32_t* pr1 = (const uint32_t*)&sP[rb + gid + 8][0];
        const uint32_t* vr  = (const uint32_t*)&sVT[nb + gid][0];
        #pragma unroll
        for (int ks = 0; ks < 4; ks++) {
            unsigned a[4] = { pr0[8*ks + tig], pr1[8*ks + tig],
                              pr0[8*ks + tig + 4], pr1[8*ks + tig + 4] };
            unsigned b[2] = { vr[8*ks + tig], vr[8*ks + tig + 4] };
            mma_f16(c, a, b);
        }
        int n0 = rb + gid, n1 = n0 + 8;
        int d = nb + 2 * tig;
        if (n0 < NTOK)
            *(__half2*)&out[(size_t)(bw * NTOK + n0) * 256 + h * HD + d] =
                __floats2half2_rn(c[0], c[1]);
        if (n1 < NTOK)
            *(__half2*)&out[(size_t)(bw * NTOK + n1) * 256 + h * HD + d] =
                __floats2half2_rn(c[2], c[3]);
    }
}

// ---------------- launcher ----------------
extern "C" void kernel_launch(void* const* d_in, const int* in_sizes, int n_in,
                              void* d_out, int out_size)
{
    (void)in_sizes; (void)n_in; (void)out_size;
    const float* x        = (const float*)d_in[0];
    const float* norm1_g  = (const float*)d_in[1];
    const float* norm1_b  = (const float*)d_in[2];
    const float* qkv_w    = (const float*)d_in[3];
    const float* qkv_b    = (const float*)d_in[4];
    const float* rel_tab  = (const float*)d_in[5];
    const float* proj_w   = (const float*)d_in[6];
    const float* proj_b   = (const float*)d_in[7];
    const float* norm2_g  = (const float*)d_in[8];
    const float* norm2_b  = (const float*)d_in[9];
    const float* fc1_w    = (const float*)d_in[10];
    const float* fc1_b    = (const float*)d_in[11];
    const float* fc2_w    = (const float*)d_in[12];
    const float* fc2_b    = (const float*)d_in[13];
    float* out = (float*)d_out;

    __half *p_a, *p_qkv, *p_h1, *p_wqkv, *p_wproj, *p_wfc1, *p_wfc2;
    float *p_xres, *p_bias;
    cudaGetSymbolAddress((void**)&p_a,     hb_a);
    cudaGetSymbolAddress((void**)&p_qkv,   hb_qkv);
    cudaGetSymbolAddress((void**)&p_h1,    hb_h1);
    cudaGetSymbolAddress((void**)&p_xres,  g_xres);
    cudaGetSymbolAddress((void**)&p_bias,  g_bias);
    cudaGetSymbolAddress((void**)&p_wqkv,  hw_qkv);
    cudaGetSymbolAddress((void**)&p_wproj, hw_proj);
    cudaGetSymbolAddress((void**)&p_wfc1,  hw_fc1);
    cudaGetSymbolAddress((void**)&p_wfc2,  hw_fc2);

    cudaFuncSetAttribute(hgemm<0>, cudaFuncAttributeMaxDynamicSharedMemorySize, GSMEM);
    cudaFuncSetAttribute(hgemm<1>, cudaFuncAttributeMaxDynamicSharedMemorySize, GSMEM);
    cudaFuncSetAttribute(hgemm<2>, cudaFuncAttributeMaxDynamicSharedMemorySize, GSMEM);
    cudaFuncSetAttribute(hgemm<3>, cudaFuncAttributeMaxDynamicSharedMemorySize, GSMEM);

    const int M = MTOK;

    // #1: weights for qkv+proj
    wconv_kernel<<<(768*256 + 256*256 + 255)/256, 256>>>(qkv_w, p_wqkv, 768*256,
                                                         proj_w, p_wproj, 256*256);
    // #2: weights for fc1+fc2
    wconv_kernel<<<(1024*256 + 256*1024 + 255)/256, 256>>>(fc1_w, p_wfc1, 1024*256,
                                                           fc2_w, p_wfc2, 256*1024);
    // #3: rel-pos bias
    bias_kernel<<<(NH*NTOK*NTOK + 255)/256, 256>>>(rel_tab, p_bias);
    // #4: LN1 + shift + window partition
    ln_kernel<1><<<M/8, 256>>>(x, p_a, norm1_g, norm1_b);
    // #5: QKV gemm  (profiled slot)
    hgemm<0><<<dim3(768/128, M/128), 256, GSMEM>>>(p_a, p_wqkv, qkv_b, nullptr, p_qkv, nullptr, M, 768, 256);
    // #6: attention
    attn_kernel<<<BW * NH, 256>>>(p_qkv, p_bias, p_a);
    // #7: proj gemm + reverse + residual
    hgemm<2><<<dim3(256/128, M/128), 256, GSMEM>>>(p_a, p_wproj, proj_b, p_xres, nullptr, x, M, 256, 256);
    // #8: LN2
    ln_kernel<0><<<M/8, 256>>>(p_xres, p_a, norm2_g, norm2_b);
    // #9: fc1 + gelu
    hgemm<1><<<dim3(1024/128, M/128), 256, GSMEM>>>(p_a, p_wfc1, fc1_b, nullptr, p_h1, nullptr, M, 1024, 256);
    // #10: fc2 + residual
    hgemm<3><<<dim3(256/128, M/128), 256, GSMEM>>>(p_h1, p_wfc2, fc2_b, out, nullptr, p_xres, M, 256, 1024);
}